// round 9
// baseline (speedup 1.0000x reference)
#include <cuda_runtime.h>
#include <cstdint>
#include <math.h>

#define BATCH 8
#define NPTS 4096

// ---------------- scratch (static device globals; no allocation) ----------------
__device__ float g_feat[BATCH*8*NPTS];
__device__ float g_h   [BATCH*32*NPTS*16];      // reused by all stages
__device__ float g_kf1 [BATCH*32*NPTS];
__device__ float g_qc1 [BATCH*3*1024];
__device__ float g_qf1 [BATCH*32*1024];
__device__ float g_qf2 [BATCH*64*1024];
__device__ float g_kf3 [BATCH*64*1024];
__device__ float g_qf4 [BATCH*64*256];
__device__ int   g_idx1[BATCH*NPTS*16];
__device__ int   g_idx2[BATCH*1024*16];
__device__ int   g_idx3[BATCH*1024*16];
__device__ int   g_idx4[BATCH*256*16];
__device__ int   g_fps1[BATCH*1024];
__device__ int   g_fps2[BATCH*256];
__device__ float g_stats[64];
__device__ float g_musig[64];

// ---------------- f32x2 packed helpers (used ONLY in fps, validated lineage) ---
__device__ __forceinline__ unsigned long long pk2(float a, float b) {
    unsigned long long r; asm("mov.b64 %0,{%1,%2};" : "=l"(r) : "f"(a), "f"(b)); return r;
}
__device__ __forceinline__ void upk2(unsigned long long v, float& a, float& b) {
    asm("mov.b64 {%0,%1},%2;" : "=f"(a), "=f"(b) : "l"(v));
}
__device__ __forceinline__ unsigned long long addx2(unsigned long long a, unsigned long long b) {
    unsigned long long r; asm("add.rn.f32x2 %0,%1,%2;" : "=l"(r) : "l"(a), "l"(b)); return r;
}
__device__ __forceinline__ unsigned long long mulx2(unsigned long long a, unsigned long long b) {
    unsigned long long r; asm("mul.rn.f32x2 %0,%1,%2;" : "=l"(r) : "l"(a), "l"(b)); return r;
}

// ---------------- pointwise transform: feat = Wt @ pc + bt ----------------
__global__ void transform_kernel(const float* __restrict__ pc, const float* __restrict__ Wt,
                                 const float* __restrict__ bt, float* __restrict__ feat)
{
    int i = blockIdx.x*256 + threadIdx.x;
    if (i >= BATCH*8*NPTS) return;
    int n = i & (NPTS-1);
    int o = (i >> 12) & 7;
    int b = i >> 15;
    const float* p = pc + (size_t)b*3*NPTS;
    float v = Wt[o*3+0]*p[n] + Wt[o*3+1]*p[NPTS+n] + Wt[o*3+2]*p[2*NPTS+n] + bt[o];
    feat[i] = v;
}

// ---------------- knn insert: predicated store + tournament rescan -------------
// Called under a warp-uniform __any_sync branch: the store is PTX-predicated
// (no inner BSSY); all lanes run the rescan (idempotent for non-acceptors).
__device__ __forceinline__ void knn_insert_any(unsigned long long (*skey)[256], int tid,
                                               bool acc, unsigned long long key,
                                               float& worstf, int& wslot)
{
    unsigned saddr = (unsigned)__cvta_generic_to_shared(&skey[wslot][tid]);
    asm volatile("{\n .reg .pred p;\n setp.ne.u32 p, %0, 0;\n @p st.shared.b64 [%1], %2;\n}"
                 :: "r"((int)acc), "r"(saddr), "l"(key) : "memory");
    unsigned long long v[8]; int ix[8];
    #pragma unroll
    for (int s = 0; s < 8; s++) {
        unsigned long long a = skey[2*s][tid], b = skey[2*s+1][tid];
        bool p = b > a;
        v[s] = p ? b : a; ix[s] = p ? 2*s+1 : 2*s;
    }
    #pragma unroll
    for (int s = 0; s < 4; s++) {
        bool p = v[2*s+1] > v[2*s];
        v[s] = p ? v[2*s+1] : v[2*s]; ix[s] = p ? ix[2*s+1] : ix[2*s];
    }
    bool pa = v[1] > v[0]; unsigned long long va = pa ? v[1] : v[0]; int ia = pa ? ix[1] : ix[0];
    bool pb = v[3] > v[2]; unsigned long long vb = pb ? v[3] : v[2]; int ib = pb ? ix[3] : ix[2];
    bool pf = vb > va;     unsigned long long w  = pf ? vb : va;     wslot = pf ? ib : ia;
    if (w == 0xFFFFFFFFFFFFFFFFULL) {
        worstf = __int_as_float(0x7f800000);           // empty slots -> +inf
    } else {
        unsigned m = (unsigned)(w >> 32);
        unsigned orig = (m & 0x80000000u) ? (m ^ 0x80000000u) : ~m;
        worstf = __uint_as_float(orig);
    }
}

// ---------------- knn device fn (full scan; used for knn3/knn4) ---------------
__device__ void knn_dev(const float* __restrict__ qb, const float* __restrict__ kb,
                        int Q, int NK, int* __restrict__ out, int qbase, char* smemraw)
{
    float4* tile = (float4*)smemraw;
    unsigned long long (*skey)[256] = (unsigned long long (*)[256])(smemraw + 16384);
    const int tid = threadIdx.x;
    const int q = qbase + tid;

    float qx = qb[q], qy = qb[Q+q], qz = qb[2*Q+q];
    float q2 = __fadd_rn(__fadd_rn(__fmul_rn(qx,qx), __fmul_rn(qy,qy)), __fmul_rn(qz,qz));

    #pragma unroll
    for (int s = 0; s < 16; s++) skey[s][tid] = 0xFFFFFFFFFFFFFFFFULL;
    float worstf = __int_as_float(0x7f800000);
    int wslot = 0;

    for (int t0 = 0; t0 < NK; t0 += 1024) {
        int tn = min(1024, NK - t0);
        __syncthreads();
        for (int i = tid; i < tn; i += 256) {
            float kx = kb[t0+i], ky = kb[NK+t0+i], kz = kb[2*NK+t0+i];
            float k2 = __fadd_rn(__fadd_rn(__fmul_rn(kx,kx), __fmul_rn(ky,ky)), __fmul_rn(kz,kz));
            tile[i] = make_float4(kx, ky, kz, k2);
        }
        __syncthreads();
        #pragma unroll 2
        for (int j = 0; j < tn; j++) {
            float4 kv = tile[j];
            float dt = __fadd_rn(__fadd_rn(__fmul_rn(qx,kv.x), __fmul_rn(qy,kv.y)), __fmul_rn(qz,kv.z));
            float d2 = __fsub_rn(__fadd_rn(q2, kv.w), __fmul_rn(2.0f, dt));
            bool acc = d2 < worstf;    // strict: equal-d2 at larger idx loses anyway
            if (__any_sync(0xFFFFFFFFu, acc)) {
                unsigned ub = __float_as_uint(d2);
                ub ^= ((int)ub < 0) ? 0xFFFFFFFFu : 0x80000000u;
                unsigned long long key = ((unsigned long long)ub << 32) | (unsigned)(t0 + j);
                knn_insert_any(skey, tid, acc, key, worstf, wslot);
            }
        }
    }
    #pragma unroll
    for (int s = 0; s < 16; s++)
        out[(size_t)q*16 + s] = (int)(skey[s][tid] & 0xFFFFFFFFu);
}

// ---------------- knn split-K device fn (knn1: 128 queries/block, parity split) -
// Thread group par=tid>>7 scans keys of parity par for query qbase+(tid&127);
// tile reads remain warp-broadcast (all lanes same j). After the scan, threads
// 0..127 select the top-16 of their two 16-slot columns. The output SET is exact
// (u64 keys carry JAX tie-breaks); downstream is order-invariant (max/sum over k).
__device__ void knn_split_dev(const float* __restrict__ qb, const float* __restrict__ kb,
                              int NK, int* __restrict__ out, int qbase, char* smemraw)
{
    float4* tile = (float4*)smemraw;
    unsigned long long (*skey)[256] = (unsigned long long (*)[256])(smemraw + 16384);
    const int tid = threadIdx.x;
    const int ql  = tid & 127;
    const int par = tid >> 7;
    const int q   = qbase + ql;

    float qx = qb[q], qy = qb[NK+q], qz = qb[2*NK+q];   // Q == NK for knn1 (self)
    float q2 = __fadd_rn(__fadd_rn(__fmul_rn(qx,qx), __fmul_rn(qy,qy)), __fmul_rn(qz,qz));

    #pragma unroll
    for (int s = 0; s < 16; s++) skey[s][tid] = 0xFFFFFFFFFFFFFFFFULL;
    float worstf = __int_as_float(0x7f800000);
    int wslot = 0;

    for (int t0 = 0; t0 < NK; t0 += 1024) {
        __syncthreads();
        for (int i = tid; i < 1024; i += 256) {
            float kx = kb[t0+i], ky = kb[NK+t0+i], kz = kb[2*NK+t0+i];
            float k2 = __fadd_rn(__fadd_rn(__fmul_rn(kx,kx), __fmul_rn(ky,ky)), __fmul_rn(kz,kz));
            tile[i] = make_float4(kx, ky, kz, k2);
        }
        __syncthreads();
        #pragma unroll 2
        for (int i = 0; i < 512; i++) {
            int j = (i << 1) | par;
            float4 kv = tile[j];
            float dt = __fadd_rn(__fadd_rn(__fmul_rn(qx,kv.x), __fmul_rn(qy,kv.y)), __fmul_rn(qz,kv.z));
            float d2 = __fsub_rn(__fadd_rn(q2, kv.w), __fmul_rn(2.0f, dt));
            bool acc = d2 < worstf;
            if (__any_sync(0xFFFFFFFFu, acc)) {
                unsigned ub = __float_as_uint(d2);
                ub ^= ((int)ub < 0) ? 0xFFFFFFFFu : 0x80000000u;
                unsigned long long key = ((unsigned long long)ub << 32) | (unsigned)(t0 + j);
                knn_insert_any(skey, tid, acc, key, worstf, wslot);
            }
        }
    }
    __syncthreads();
    if (tid < 128) {
        for (int r = 0; r < 16; r++) {
            unsigned long long best = 0xFFFFFFFFFFFFFFFFULL; int bs = 0;
            #pragma unroll
            for (int s = 0; s < 32; s++) {
                unsigned long long vv = (s < 16) ? skey[s][tid] : skey[s-16][tid+128];
                if (vv < best) { best = vv; bs = s; }
            }
            out[(size_t)q*16 + r] = (int)(best & 0xFFFFFFFFu);
            if (bs < 16) skey[bs][tid] = 0xFFFFFFFFFFFFFFFFULL;
            else         skey[bs-16][tid+128] = 0xFFFFFFFFFFFFFFFFULL;
        }
    }
}

// ---------------- FPS device function (r4-proven form: 1 barrier/iter) --------
template<int NP, int M>
__device__ void fps_dev(const float* __restrict__ cb, int* __restrict__ outi, char* smemraw)
{
    constexpr int PPT = NP / 256;
    constexpr int PAIRS = PPT / 2;
    static_assert(PPT * 256 == NP && PAIRS * 2 == PPT, "layout");
    const int tid  = threadIdx.x;
    const int warp = tid >> 5;
    unsigned long long (*skeys)[8] = (unsigned long long (*)[8])smemraw;   // [2][8]

    unsigned long long xp[PAIRS], yp[PAIRS], zp[PAIRS];
    float d_[PPT];
    #pragma unroll
    for (int pr = 0; pr < PAIRS; pr++) {
        int i0 = (2*pr)*256 + tid, i1 = (2*pr+1)*256 + tid;
        xp[pr] = pk2(cb[i0],        cb[i1]);
        yp[pr] = pk2(cb[NP+i0],     cb[NP+i1]);
        zp[pr] = pk2(cb[2*NP+i0],   cb[2*NP+i1]);
        d_[2*pr] = 1e10f; d_[2*pr+1] = 1e10f;
    }
    if (tid == 0) outi[0] = 0;

    int last = 0;
    for (int t = 1; t < M; t++) {
        float px = __ldg(cb + last), py = __ldg(cb + NP + last), pz = __ldg(cb + 2*NP + last);
        unsigned long long pxn = pk2(-px, -px), pyn = pk2(-py, -py), pzn = pk2(-pz, -pz);
        float bestd = -1.0f; int besti = 0;
        #pragma unroll
        for (int pr = 0; pr < PAIRS; pr++) {
            // exact reference sequence per lane: sub, 3x mul, 2x add (NO fma)
            unsigned long long dx = addx2(xp[pr], pxn);
            unsigned long long dy = addx2(yp[pr], pyn);
            unsigned long long dz = addx2(zp[pr], pzn);
            unsigned long long s2 = addx2(addx2(mulx2(dx,dx), mulx2(dy,dy)), mulx2(dz,dz));
            float m0, m1; upk2(s2, m0, m1);
            float d0 = fminf(d_[2*pr],   m0); d_[2*pr]   = d0;
            float d1 = fminf(d_[2*pr+1], m1); d_[2*pr+1] = d1;
            if (d0 > bestd) { bestd = d0; besti = (2*pr)*256 + tid; }
            if (d1 > bestd) { bestd = d1; besti = (2*pr+1)*256 + tid; }
        }
        unsigned db     = __float_as_uint(bestd);          // d >= 0 so bits ordered
        unsigned rmax   = __reduce_max_sync(0xFFFFFFFFu, db);
        unsigned inv    = (db == rmax) ? (0xFFFFFFFFu - (unsigned)besti) : 0u;
        unsigned invmax = __reduce_max_sync(0xFFFFFFFFu, inv);
        if ((tid & 31) == 0)
            skeys[t & 1][warp] = ((unsigned long long)rmax << 32) | invmax;
        __syncthreads();
        const unsigned long long* kk = skeys[t & 1];
        unsigned long long k0 = kk[0] > kk[1] ? kk[0] : kk[1];
        unsigned long long k1 = kk[2] > kk[3] ? kk[2] : kk[3];
        unsigned long long k2 = kk[4] > kk[5] ? kk[4] : kk[5];
        unsigned long long k3 = kk[6] > kk[7] ? kk[6] : kk[7];
        k0 = k0 > k1 ? k0 : k1;
        k2 = k2 > k3 ? k2 : k3;
        k0 = k0 > k2 ? k0 : k2;
        last = (int)(0xFFFFFFFFu - (unsigned)(k0 & 0xFFFFFFFFu));
        if (tid == 0) outi[t] = last;
    }
}

// ---------------- edge conv pass 1 device fn: h = W @ [neigh-qe; qe] + stats ---
template<int C, int O>
__device__ void edge_h_dev(const float* __restrict__ kf, const float* __restrict__ qf,
                           const int* __restrict__ idx, const float* __restrict__ W,
                           float* __restrict__ h, float* __restrict__ stats,
                           int Q, int NK, int b, int qbase, char* smemraw)
{
    float* sW   = (float*)smemraw;      // O*2C
    float* sqf  = sW  + O*2*C;          // [c*16+ql]
    float* sqb  = sqf + C*16;           // [ql*O+o]
    float* sred = sqb + 16*O;           // 8 warps * 8

    const int tid = threadIdx.x;

    for (int i = tid; i < O*2*C; i += 256) sW[i] = W[i];
    for (int i = tid; i < C*16;  i += 256)
        sqf[i] = qf[((size_t)b*C + (i >> 4))*Q + qbase + (i & 15)];
    __syncthreads();

    for (int e = tid; e < 16*O; e += 256) {
        int ql = e / O, o = e - ql*O;
        float acc = 0.f;
        #pragma unroll
        for (int c = 0; c < C; c++) acc = fmaf(sW[o*2*C + C + c], sqf[c*16 + ql], acc);
        sqb[e] = acc;
    }
    __syncthreads();

    const int ql = tid >> 4, k = tid & 15;
    const int q = qbase + ql;
    const int j = idx[((size_t)b*Q + q)*16 + k];

    float e_[C];
    #pragma unroll
    for (int c = 0; c < C; c++)
        e_[c] = kf[((size_t)b*C + c)*NK + j] - sqf[c*16 + ql];

    float* hp = h + ((size_t)b*O*Q + q)*16 + k;
    const float* sqbp = sqb + ql*O;
    const int lane = tid & 31, warp = tid >> 5;

    #pragma unroll
    for (int g = 0; g < 4; g++) {
        float s = 0.f, ss = 0.f;
        for (int o = g*(O/4); o < (g+1)*(O/4); o++) {
            float acc = sqbp[o];
            const float* wr = sW + o*2*C;
            #pragma unroll
            for (int c = 0; c < C; c++) acc = fmaf(wr[c], e_[c], acc);
            hp[(size_t)o*Q*16] = acc;
            s += acc; ss = fmaf(acc, acc, ss);
        }
        #pragma unroll
        for (int off = 16; off; off >>= 1) {
            s  += __shfl_xor_sync(0xFFFFFFFFu, s,  off);
            ss += __shfl_xor_sync(0xFFFFFFFFu, ss, off);
        }
        if (lane == 0) { sred[warp*8 + g*2] = s; sred[warp*8 + g*2 + 1] = ss; }
    }
    __syncthreads();
    if (tid < 8) {
        float t = 0.f;
        #pragma unroll
        for (int w = 0; w < 8; w++) t += sred[w*8 + tid];
        atomicAdd(&stats[b*8 + tid], t);
    }
}

// ---------------- mega kernel 1: knn1 split-K (256 blocks) || fps1 (8) ---------
// 264 blocks -> ~2 blocks/SM: doubles warp supply for the stall-bound knn scan.
__global__ void __launch_bounds__(256, 2) mega1_kernel(const float* __restrict__ pc,
                                                       int* __restrict__ idx1,
                                                       int* __restrict__ fps1)
{
    extern __shared__ char smem[];
    int blk = blockIdx.x;
    if (blk < 256) {
        int b = blk >> 5, chunk = blk & 31;            // 32 chunks x 128 queries
        knn_split_dev(pc + (size_t)b*3*NPTS, pc + (size_t)b*3*NPTS, NPTS,
                      idx1 + (size_t)b*NPTS*16, chunk*128, smem);
    } else {
        int b = blk - 256;
        fps_dev<4096,1024>(pc + (size_t)b*3*NPTS, fps1 + (size_t)b*1024, smem);
    }
}

// ---------------- fused kernel 2: knn3 (32) || fps2 (8) || edge1_h (2048) ------
__global__ void __launch_bounds__(256) fused2_kernel(const float* __restrict__ qc1,
                                                     const float* __restrict__ feat,
                                                     const int* __restrict__ idx1,
                                                     const float* __restrict__ W1,
                                                     float* __restrict__ h,
                                                     float* __restrict__ stats,
                                                     int* __restrict__ idx3,
                                                     int* __restrict__ fps2)
{
    extern __shared__ char smem[];
    int blk = blockIdx.x;
    if (blk < 32) {
        int b = blk >> 2, chunk = blk & 3;
        knn_dev(qc1 + (size_t)b*3*1024, qc1 + (size_t)b*3*1024, 1024, 1024,
                idx3 + (size_t)b*1024*16, chunk*256, smem);
    } else if (blk < 40) {
        int b = blk - 32;
        fps_dev<1024,256>(qc1 + (size_t)b*3*1024, fps2 + (size_t)b*256, smem);
    } else {
        int e = blk - 40;                 // 0..2047
        int b = e >> 8, qt = e & 255;
        edge_h_dev<8,32>(feat, feat, idx1, W1, h, stats, NPTS, NPTS, b, qt*16, smem);
    }
}

// ---------------- idx2 = idx1[fps1] (knn2 elimination) -------------------------
__global__ void idx2_gather_kernel(const int* __restrict__ idx1, const int* __restrict__ fps1,
                                   int* __restrict__ idx2)
{
    int i = blockIdx.x*256 + threadIdx.x;          // over B*1024*16
    if (i >= BATCH*1024*16) return;
    int s = i & 15; int m = (i >> 4) & 1023; int b = i >> 14;
    idx2[i] = idx1[((size_t)b*NPTS + fps1[b*1024 + m])*16 + s];
}

// ---------------- knn4 (needs gathered out coords) ----------------
__global__ void __launch_bounds__(256) knn4_kernel(const float* __restrict__ qc,
                                                   int* __restrict__ idx4)
{
    extern __shared__ char smem[];
    int b = blockIdx.x;
    knn_dev(qc + (size_t)b*3*256, qc + (size_t)b*3*256, 256, 256,
            idx4 + (size_t)b*256*16, 0, smem);
}

// ---------------- gather: dst[b,c,m] = src[b,c,idx[b,m]] ----------------
__global__ void gather_kernel(const float* __restrict__ src, const int* __restrict__ idx,
                              float* __restrict__ dst, int C, int Nsrc, int M)
{
    int i = blockIdx.x*256 + threadIdx.x;
    if (i >= BATCH*C*M) return;
    int m = i % M; int c = (i/M) % C; int b = i/(M*C);
    dst[i] = src[((size_t)b*C + c)*Nsrc + idx[(size_t)b*M + m]];
}

// ---------------- edge conv wrappers (stages 2,3,4) ----------------
template<int C, int O>
__global__ void edge_h_kernel(const float* __restrict__ kf, const float* __restrict__ qf,
                              const int* __restrict__ idx, const float* __restrict__ W,
                              float* __restrict__ h, float* __restrict__ stats,
                              int Q, int NK)
{
    extern __shared__ char smemc[];
    edge_h_dev<C,O>(kf, qf, idx, W, h, stats, Q, NK, blockIdx.y, blockIdx.x*16, smemc);
}

// ---------------- stats ----------------
__global__ void zero_stats_kernel(float* __restrict__ stats)
{
    int i = threadIdx.x;
    if (i < 64) stats[i] = 0.f;
}
__global__ void stats_fin_kernel(const float* __restrict__ stats, float* __restrict__ musig,
                                 float inv_cnt)
{
    int i = threadIdx.x;
    if (i < 32) {
        float s = stats[i*2], ss = stats[i*2+1];
        float mu  = s * inv_cnt;
        float var = ss * inv_cnt - mu*mu;
        musig[i*2]   = mu;
        musig[i*2+1] = 1.0f / sqrtf(var + 1e-5f);
    }
}

// ---------------- edge conv pass 2: GN + leaky + max over k ----------------
__global__ void edge_out_kernel(const float* __restrict__ h, const float* __restrict__ musig,
                                const float* __restrict__ gamma, const float* __restrict__ beta,
                                float* __restrict__ out, int O, int O4, int Q)
{
    int i = blockIdx.x*256 + threadIdx.x;
    if (i >= BATCH*O*Q) return;
    int o = (i / Q) % O;
    int b = i / (Q*O);
    int g = o / O4;
    float mu   = musig[(b*4+g)*2];
    float rstd = musig[(b*4+g)*2+1];
    float ga = gamma[o], be = beta[o];
    const float4* hp = (const float4*)(h + (size_t)i*16);
    float m = -INFINITY;
    #pragma unroll
    for (int r = 0; r < 4; r++) {
        float4 v = hp[r];
        float vv[4] = {v.x, v.y, v.z, v.w};
        #pragma unroll
        for (int c = 0; c < 4; c++) {
            float xn = (vv[c] - mu) * rstd;
            float y  = xn * ga + be;
            y = (y >= 0.f) ? y : 0.2f * y;
            m = fmaxf(m, y);
        }
    }
    out[i] = m;
}

// ---------------- host orchestration ----------------
static inline int eh_smem(int C, int O) { return (O*2*C + 16*C + 16*O + 64) * 4; }
#define KNN_SMEM 49152

extern "C" void kernel_launch(void* const* d_in, const int* in_sizes, int n_in,
                              void* d_out, int out_size)
{
    const float* pc = (const float*)d_in[0];
    const float* Wt = (const float*)d_in[1];
    const float* bt = (const float*)d_in[2];
    const float* W1 = (const float*)d_in[3];
    const float* g1 = (const float*)d_in[4];
    const float* b1 = (const float*)d_in[5];
    const float* W2 = (const float*)d_in[6];
    const float* g2 = (const float*)d_in[7];
    const float* b2 = (const float*)d_in[8];
    const float* W3 = (const float*)d_in[9];
    const float* g3 = (const float*)d_in[10];
    const float* b3 = (const float*)d_in[11];
    const float* W4 = (const float*)d_in[12];
    const float* g4 = (const float*)d_in[13];
    const float* b4 = (const float*)d_in[14];
    float* out = (float*)d_out;

    float *feat, *h, *kf1, *qc1, *qf1, *qf2, *kf3, *qf4, *stats, *musig;
    int *idx1, *idx2, *idx3, *idx4, *fps1, *fps2;
    cudaGetSymbolAddress((void**)&feat,  g_feat);
    cudaGetSymbolAddress((void**)&h,     g_h);
    cudaGetSymbolAddress((void**)&kf1,   g_kf1);
    cudaGetSymbolAddress((void**)&qc1,   g_qc1);
    cudaGetSymbolAddress((void**)&qf1,   g_qf1);
    cudaGetSymbolAddress((void**)&qf2,   g_qf2);
    cudaGetSymbolAddress((void**)&kf3,   g_kf3);
    cudaGetSymbolAddress((void**)&qf4,   g_qf4);
    cudaGetSymbolAddress((void**)&stats, g_stats);
    cudaGetSymbolAddress((void**)&musig, g_musig);
    cudaGetSymbolAddress((void**)&idx1,  g_idx1);
    cudaGetSymbolAddress((void**)&idx2,  g_idx2);
    cudaGetSymbolAddress((void**)&idx3,  g_idx3);
    cudaGetSymbolAddress((void**)&idx4,  g_idx4);
    cudaGetSymbolAddress((void**)&fps1,  g_fps1);
    cudaGetSymbolAddress((void**)&fps2,  g_fps2);

    cudaFuncSetAttribute(edge_h_kernel<64,128>,
                         cudaFuncAttributeMaxDynamicSharedMemorySize, eh_smem(64,128));

    // launches 1-3 (pads mega1 into the ncu capture slot)
    transform_kernel<<<(BATCH*8*NPTS+255)/256, 256>>>(pc, Wt, bt, feat);
    zero_stats_kernel<<<1,64>>>(stats);
    zero_stats_kernel<<<1,64>>>(stats);

    // launch #4: mega1 = knn1 split-K (256) || fps1 (8)
    mega1_kernel<<<264, 256, KNN_SMEM>>>(pc, idx1, fps1);

    // qc1 gather (only fps1-dependent; unblocks fused2)
    gather_kernel<<<(BATCH*3*1024+255)/256, 256>>>(pc, fps1, qc1, 3, NPTS, 1024);

    // fused2: knn3 (32) || fps2 (8) || edge1_h (2048)
    fused2_kernel<<<2088, 256, KNN_SMEM>>>(qc1, feat, idx1, W1, h, stats, idx3, fps2);

    // idx2 = idx1[fps1]  (knn2 eliminated)
    idx2_gather_kernel<<<(BATCH*1024*16+255)/256, 256>>>(idx1, fps1, idx2);

    // edge_conv 1 epilogue
    stats_fin_kernel<<<1,32>>>(stats, musig, 1.0f/524288.0f);
    edge_out_kernel<<<(BATCH*32*NPTS+255)/256, 256>>>(h, musig, g1, b1, kf1, 32, 8, NPTS);
    gather_kernel<<<(BATCH*32*1024+255)/256,256>>>(kf1, fps1, qf1, 32, NPTS, 1024);

    // edge_conv 2: C=32 -> O=64 (idx2, keys = full 4096 set)
    zero_stats_kernel<<<1,64>>>(stats);
    edge_h_kernel<32,64><<<dim3(1024/16, BATCH), 256, eh_smem(32,64)>>>(kf1, qf1, idx2, W2, h, stats, 1024, NPTS);
    stats_fin_kernel<<<1,32>>>(stats, musig, 1.0f/262144.0f);
    edge_out_kernel<<<(BATCH*64*1024+255)/256, 256>>>(h, musig, g2, b2, qf2, 64, 16, 1024);

    // edge_conv 3: C=64 -> O=64 (idx3 from fused2)
    zero_stats_kernel<<<1,64>>>(stats);
    edge_h_kernel<64,64><<<dim3(1024/16, BATCH), 256, eh_smem(64,64)>>>(qf2, qf2, idx3, W3, h, stats, 1024, 1024);
    stats_fin_kernel<<<1,32>>>(stats, musig, 1.0f/262144.0f);
    edge_out_kernel<<<(BATCH*64*1024+255)/256, 256>>>(h, musig, g3, b3, kf3, 64, 16, 1024);

    // fps2 gathers (coords straight into d_out) + knn4
    gather_kernel<<<(BATCH*3*256+255)/256, 256>>>(qc1, fps2, out, 3, 1024, 256);
    gather_kernel<<<(BATCH*64*256+255)/256,256>>>(kf3, fps2, qf4, 64, 1024, 256);
    knn4_kernel<<<8, 256, KNN_SMEM>>>(out, idx4);

    // edge_conv 4: C=64 -> O=128
    zero_stats_kernel<<<1,64>>>(stats);
    edge_h_kernel<64,128><<<dim3(256/16, BATCH), 256, eh_smem(64,128)>>>(qf4, qf4, idx4, W4, h, stats, 256, 256);
    stats_fin_kernel<<<1,32>>>(stats, musig, 1.0f/131072.0f);
    edge_out_kernel<<<(BATCH*128*256+255)/256, 256>>>(h, musig, g4, b4, out + BATCH*3*256, 128, 32, 256);
}

// round 10
// speedup vs baseline: 1.1807x; 1.1807x over previous
#include <cuda_runtime.h>
#include <cstdint>
#include <math.h>

#define BATCH 8
#define NPTS 4096

// ---------------- scratch (static device globals; no allocation) ----------------
__device__ float g_feat[BATCH*8*NPTS];
__device__ float g_h   [BATCH*32*NPTS*16];      // reused by all stages
__device__ float g_kf1 [BATCH*32*NPTS];
__device__ float g_qc1 [BATCH*3*1024];
__device__ float g_qf1 [BATCH*32*1024];
__device__ float g_qf2 [BATCH*64*1024];
__device__ float g_kf3 [BATCH*64*1024];
__device__ float g_qf4 [BATCH*64*256];
__device__ int   g_idx1[BATCH*NPTS*16];
__device__ int   g_idx2[BATCH*1024*16];
__device__ int   g_idx3[BATCH*1024*16];
__device__ int   g_idx4[BATCH*256*16];
__device__ int   g_fps1[BATCH*1024];
__device__ int   g_fps2[BATCH*256];
__device__ float g_stats[64];
__device__ float g_musig[64];

// ---------------- f32x2 packed helpers (used ONLY in fps, validated lineage) ---
__device__ __forceinline__ unsigned long long pk2(float a, float b) {
    unsigned long long r; asm("mov.b64 %0,{%1,%2};" : "=l"(r) : "f"(a), "f"(b)); return r;
}
__device__ __forceinline__ void upk2(unsigned long long v, float& a, float& b) {
    asm("mov.b64 {%0,%1},%2;" : "=f"(a), "=f"(b) : "l"(v));
}
__device__ __forceinline__ unsigned long long addx2(unsigned long long a, unsigned long long b) {
    unsigned long long r; asm("add.rn.f32x2 %0,%1,%2;" : "=l"(r) : "l"(a), "l"(b)); return r;
}
__device__ __forceinline__ unsigned long long mulx2(unsigned long long a, unsigned long long b) {
    unsigned long long r; asm("mul.rn.f32x2 %0,%1,%2;" : "=l"(r) : "l"(a), "l"(b)); return r;
}

// ---------------- pointwise transform: feat = Wt @ pc + bt ----------------
__global__ void transform_kernel(const float* __restrict__ pc, const float* __restrict__ Wt,
                                 const float* __restrict__ bt, float* __restrict__ feat)
{
    int i = blockIdx.x*256 + threadIdx.x;
    if (i >= BATCH*8*NPTS) return;
    int n = i & (NPTS-1);
    int o = (i >> 12) & 7;
    int b = i >> 15;
    const float* p = pc + (size_t)b*3*NPTS;
    float v = Wt[o*3+0]*p[n] + Wt[o*3+1]*p[NPTS+n] + Wt[o*3+2]*p[2*NPTS+n] + bt[o];
    feat[i] = v;
}

// ---------------- knn insert: group-max cached, O(4) rescan --------------------
// skey[16][256] column-per-thread in shared; gmax[4]/gslot[4] cache each group's
// max key+slot in registers. Insert: predicated STS at the tracked worst slot,
// reload ONLY that group (4 LDS.64), 3-node u64 tree, predicated scatter into
// the reg cache, 3-node global tree. Keys are unique (idx in low bits) so all
// compares are tie-free; ALL-ONES = empty = always evicted first (JAX-exact).
// Safe for non-accepting lanes under __any_sync: their store is predicated off
// and the recompute is idempotent.
__device__ __forceinline__ void knn_insert_grp(unsigned skeybase,
        unsigned long long (*skey)[256], int tid, bool acc, unsigned long long key,
        unsigned long long* gmax, int* gslot,
        unsigned long long& worst, int& wslot, float& worstf)
{
    unsigned saddr = skeybase + (unsigned)(wslot*2048 + tid*8);
    asm volatile("{\n .reg .pred p;\n setp.ne.u32 p, %0, 0;\n @p st.shared.b64 [%1], %2;\n}"
                 :: "r"((int)acc), "r"(saddr), "l"(key) : "memory");
    const int g = wslot >> 2;
    unsigned long long a = skey[(g<<2)+0][tid];
    unsigned long long b = skey[(g<<2)+1][tid];
    unsigned long long c = skey[(g<<2)+2][tid];
    unsigned long long d = skey[(g<<2)+3][tid];
    bool p1 = b > a; unsigned long long m1 = p1?b:a; int s1 = (g<<2)|(int)p1;
    bool p2 = d > c; unsigned long long m2 = p2?d:c; int s2 = (g<<2)|2|(int)p2;
    bool pf = m2 > m1; unsigned long long ng = pf?m2:m1; int ns = pf?s2:s1;
    #pragma unroll
    for (int s = 0; s < 4; s++) {
        bool pe = (g == s);
        gmax[s]  = pe ? ng : gmax[s];
        gslot[s] = pe ? ns : gslot[s];
    }
    bool q1 = gmax[1] > gmax[0]; unsigned long long w1 = q1?gmax[1]:gmax[0]; int u1 = q1?gslot[1]:gslot[0];
    bool q2 = gmax[3] > gmax[2]; unsigned long long w2 = q2?gmax[3]:gmax[2]; int u2 = q2?gslot[3]:gslot[2];
    bool qf = w2 > w1; worst = qf?w2:w1; wslot = qf?u2:u1;
    if (worst == 0xFFFFFFFFFFFFFFFFULL) {
        worstf = __int_as_float(0x7f800000);
    } else {
        unsigned m = (unsigned)(worst >> 32);
        unsigned orig = (m & 0x80000000u) ? (m ^ 0x80000000u) : ~m;
        worstf = __uint_as_float(orig);
    }
}

// ---------------- knn device fn (full scan; used for knn3/knn4) ---------------
__device__ void knn_dev(const float* __restrict__ qb, const float* __restrict__ kb,
                        int Q, int NK, int* __restrict__ out, int qbase, char* smemraw)
{
    float4* tile = (float4*)smemraw;
    unsigned long long (*skey)[256] = (unsigned long long (*)[256])(smemraw + 16384);
    const int tid = threadIdx.x;
    const int q = qbase + tid;
    unsigned skeybase = (unsigned)__cvta_generic_to_shared(&skey[0][0]);

    float qx = qb[q], qy = qb[Q+q], qz = qb[2*Q+q];
    float q2 = __fadd_rn(__fadd_rn(__fmul_rn(qx,qx), __fmul_rn(qy,qy)), __fmul_rn(qz,qz));

    #pragma unroll
    for (int s = 0; s < 16; s++) skey[s][tid] = 0xFFFFFFFFFFFFFFFFULL;
    unsigned long long gmax[4]; int gslot[4];
    #pragma unroll
    for (int s = 0; s < 4; s++) { gmax[s] = 0xFFFFFFFFFFFFFFFFULL; gslot[s] = s<<2; }
    unsigned long long worst = 0xFFFFFFFFFFFFFFFFULL;
    float worstf = __int_as_float(0x7f800000);
    int wslot = 0;

    for (int t0 = 0; t0 < NK; t0 += 1024) {
        int tn = min(1024, NK - t0);
        __syncthreads();
        for (int i = tid; i < tn; i += 256) {
            float kx = kb[t0+i], ky = kb[NK+t0+i], kz = kb[2*NK+t0+i];
            float k2 = __fadd_rn(__fadd_rn(__fmul_rn(kx,kx), __fmul_rn(ky,ky)), __fmul_rn(kz,kz));
            tile[i] = make_float4(kx, ky, kz, k2);
        }
        __syncthreads();
        #pragma unroll 2
        for (int j = 0; j < tn; j++) {
            float4 kv = tile[j];
            float dt = __fadd_rn(__fadd_rn(__fmul_rn(qx,kv.x), __fmul_rn(qy,kv.y)), __fmul_rn(qz,kv.z));
            float d2 = __fsub_rn(__fadd_rn(q2, kv.w), __fmul_rn(2.0f, dt));
            bool acc = d2 < worstf;    // strict: equal-d2 at larger idx loses anyway
            if (__any_sync(0xFFFFFFFFu, acc)) {
                unsigned ub = __float_as_uint(d2);
                ub ^= ((int)ub < 0) ? 0xFFFFFFFFu : 0x80000000u;
                unsigned long long key = ((unsigned long long)ub << 32) | (unsigned)(t0 + j);
                knn_insert_grp(skeybase, skey, tid, acc, key, gmax, gslot, worst, wslot, worstf);
            }
        }
    }
    #pragma unroll
    for (int s = 0; s < 16; s++)
        out[(size_t)q*16 + s] = (int)(skey[s][tid] & 0xFFFFFFFFu);
}

// ---------------- knn split-K device fn (knn1: 128 queries/block, parity split) -
__device__ void knn_split_dev(const float* __restrict__ qb, const float* __restrict__ kb,
                              int NK, int* __restrict__ out, int qbase, char* smemraw)
{
    float4* tile = (float4*)smemraw;
    unsigned long long (*skey)[256] = (unsigned long long (*)[256])(smemraw + 16384);
    const int tid = threadIdx.x;
    const int ql  = tid & 127;
    const int par = tid >> 7;
    const int q   = qbase + ql;
    unsigned skeybase = (unsigned)__cvta_generic_to_shared(&skey[0][0]);

    float qx = qb[q], qy = qb[NK+q], qz = qb[2*NK+q];   // Q == NK for knn1 (self)
    float q2 = __fadd_rn(__fadd_rn(__fmul_rn(qx,qx), __fmul_rn(qy,qy)), __fmul_rn(qz,qz));

    #pragma unroll
    for (int s = 0; s < 16; s++) skey[s][tid] = 0xFFFFFFFFFFFFFFFFULL;
    unsigned long long gmax[4]; int gslot[4];
    #pragma unroll
    for (int s = 0; s < 4; s++) { gmax[s] = 0xFFFFFFFFFFFFFFFFULL; gslot[s] = s<<2; }
    unsigned long long worst = 0xFFFFFFFFFFFFFFFFULL;
    float worstf = __int_as_float(0x7f800000);
    int wslot = 0;

    for (int t0 = 0; t0 < NK; t0 += 1024) {
        __syncthreads();
        for (int i = tid; i < 1024; i += 256) {
            float kx = kb[t0+i], ky = kb[NK+t0+i], kz = kb[2*NK+t0+i];
            float k2 = __fadd_rn(__fadd_rn(__fmul_rn(kx,kx), __fmul_rn(ky,ky)), __fmul_rn(kz,kz));
            tile[i] = make_float4(kx, ky, kz, k2);
        }
        __syncthreads();
        #pragma unroll 2
        for (int i = 0; i < 512; i++) {
            int j = (i << 1) | par;
            float4 kv = tile[j];
            float dt = __fadd_rn(__fadd_rn(__fmul_rn(qx,kv.x), __fmul_rn(qy,kv.y)), __fmul_rn(qz,kv.z));
            float d2 = __fsub_rn(__fadd_rn(q2, kv.w), __fmul_rn(2.0f, dt));
            bool acc = d2 < worstf;
            if (__any_sync(0xFFFFFFFFu, acc)) {
                unsigned ub = __float_as_uint(d2);
                ub ^= ((int)ub < 0) ? 0xFFFFFFFFu : 0x80000000u;
                unsigned long long key = ((unsigned long long)ub << 32) | (unsigned)(t0 + j);
                knn_insert_grp(skeybase, skey, tid, acc, key, gmax, gslot, worst, wslot, worstf);
            }
        }
    }
    __syncthreads();
    if (tid < 128) {
        for (int r = 0; r < 16; r++) {
            unsigned long long best = 0xFFFFFFFFFFFFFFFFULL; int bs = 0;
            #pragma unroll
            for (int s = 0; s < 32; s++) {
                unsigned long long vv = (s < 16) ? skey[s][tid] : skey[s-16][tid+128];
                if (vv < best) { best = vv; bs = s; }
            }
            out[(size_t)q*16 + r] = (int)(best & 0xFFFFFFFFu);
            if (bs < 16) skey[bs][tid] = 0xFFFFFFFFFFFFFFFFULL;
            else         skey[bs-16][tid+128] = 0xFFFFFFFFFFFFFFFFULL;
        }
    }
}

// ---------------- FPS device function (r4-proven form: 1 barrier/iter) --------
template<int NP, int M>
__device__ void fps_dev(const float* __restrict__ cb, int* __restrict__ outi, char* smemraw)
{
    constexpr int PPT = NP / 256;
    constexpr int PAIRS = PPT / 2;
    static_assert(PPT * 256 == NP && PAIRS * 2 == PPT, "layout");
    const int tid  = threadIdx.x;
    const int warp = tid >> 5;
    unsigned long long (*skeys)[8] = (unsigned long long (*)[8])smemraw;   // [2][8]

    unsigned long long xp[PAIRS], yp[PAIRS], zp[PAIRS];
    float d_[PPT];
    #pragma unroll
    for (int pr = 0; pr < PAIRS; pr++) {
        int i0 = (2*pr)*256 + tid, i1 = (2*pr+1)*256 + tid;
        xp[pr] = pk2(cb[i0],        cb[i1]);
        yp[pr] = pk2(cb[NP+i0],     cb[NP+i1]);
        zp[pr] = pk2(cb[2*NP+i0],   cb[2*NP+i1]);
        d_[2*pr] = 1e10f; d_[2*pr+1] = 1e10f;
    }
    if (tid == 0) outi[0] = 0;

    int last = 0;
    for (int t = 1; t < M; t++) {
        float px = __ldg(cb + last), py = __ldg(cb + NP + last), pz = __ldg(cb + 2*NP + last);
        unsigned long long pxn = pk2(-px, -px), pyn = pk2(-py, -py), pzn = pk2(-pz, -pz);
        float bestd = -1.0f; int besti = 0;
        #pragma unroll
        for (int pr = 0; pr < PAIRS; pr++) {
            // exact reference sequence per lane: sub, 3x mul, 2x add (NO fma)
            unsigned long long dx = addx2(xp[pr], pxn);
            unsigned long long dy = addx2(yp[pr], pyn);
            unsigned long long dz = addx2(zp[pr], pzn);
            unsigned long long s2 = addx2(addx2(mulx2(dx,dx), mulx2(dy,dy)), mulx2(dz,dz));
            float m0, m1; upk2(s2, m0, m1);
            float d0 = fminf(d_[2*pr],   m0); d_[2*pr]   = d0;
            float d1 = fminf(d_[2*pr+1], m1); d_[2*pr+1] = d1;
            if (d0 > bestd) { bestd = d0; besti = (2*pr)*256 + tid; }
            if (d1 > bestd) { bestd = d1; besti = (2*pr+1)*256 + tid; }
        }
        unsigned db     = __float_as_uint(bestd);          // d >= 0 so bits ordered
        unsigned rmax   = __reduce_max_sync(0xFFFFFFFFu, db);
        unsigned inv    = (db == rmax) ? (0xFFFFFFFFu - (unsigned)besti) : 0u;
        unsigned invmax = __reduce_max_sync(0xFFFFFFFFu, inv);
        if ((tid & 31) == 0)
            skeys[t & 1][warp] = ((unsigned long long)rmax << 32) | invmax;
        __syncthreads();
        const unsigned long long* kk = skeys[t & 1];
        unsigned long long k0 = kk[0] > kk[1] ? kk[0] : kk[1];
        unsigned long long k1 = kk[2] > kk[3] ? kk[2] : kk[3];
        unsigned long long k2 = kk[4] > kk[5] ? kk[4] : kk[5];
        unsigned long long k3 = kk[6] > kk[7] ? kk[6] : kk[7];
        k0 = k0 > k1 ? k0 : k1;
        k2 = k2 > k3 ? k2 : k3;
        k0 = k0 > k2 ? k0 : k2;
        last = (int)(0xFFFFFFFFu - (unsigned)(k0 & 0xFFFFFFFFu));
        if (tid == 0) outi[t] = last;
    }
}

// ---------------- edge conv pass 1 device fn: h = W @ [neigh-qe; qe] + stats ---
template<int C, int O>
__device__ void edge_h_dev(const float* __restrict__ kf, const float* __restrict__ qf,
                           const int* __restrict__ idx, const float* __restrict__ W,
                           float* __restrict__ h, float* __restrict__ stats,
                           int Q, int NK, int b, int qbase, char* smemraw)
{
    float* sW   = (float*)smemraw;      // O*2C
    float* sqf  = sW  + O*2*C;          // [c*16+ql]
    float* sqb  = sqf + C*16;           // [ql*O+o]
    float* sred = sqb + 16*O;           // 8 warps * 8

    const int tid = threadIdx.x;

    for (int i = tid; i < O*2*C; i += 256) sW[i] = W[i];
    for (int i = tid; i < C*16;  i += 256)
        sqf[i] = qf[((size_t)b*C + (i >> 4))*Q + qbase + (i & 15)];
    __syncthreads();

    for (int e = tid; e < 16*O; e += 256) {
        int ql = e / O, o = e - ql*O;
        float acc = 0.f;
        #pragma unroll
        for (int c = 0; c < C; c++) acc = fmaf(sW[o*2*C + C + c], sqf[c*16 + ql], acc);
        sqb[e] = acc;
    }
    __syncthreads();

    const int ql = tid >> 4, k = tid & 15;
    const int q = qbase + ql;
    const int j = idx[((size_t)b*Q + q)*16 + k];

    float e_[C];
    #pragma unroll
    for (int c = 0; c < C; c++)
        e_[c] = kf[((size_t)b*C + c)*NK + j] - sqf[c*16 + ql];

    float* hp = h + ((size_t)b*O*Q + q)*16 + k;
    const float* sqbp = sqb + ql*O;
    const int lane = tid & 31, warp = tid >> 5;

    #pragma unroll
    for (int g = 0; g < 4; g++) {
        float s = 0.f, ss = 0.f;
        for (int o = g*(O/4); o < (g+1)*(O/4); o++) {
            float acc = sqbp[o];
            const float* wr = sW + o*2*C;
            #pragma unroll
            for (int c = 0; c < C; c++) acc = fmaf(wr[c], e_[c], acc);
            hp[(size_t)o*Q*16] = acc;
            s += acc; ss = fmaf(acc, acc, ss);
        }
        #pragma unroll
        for (int off = 16; off; off >>= 1) {
            s  += __shfl_xor_sync(0xFFFFFFFFu, s,  off);
            ss += __shfl_xor_sync(0xFFFFFFFFu, ss, off);
        }
        if (lane == 0) { sred[warp*8 + g*2] = s; sred[warp*8 + g*2 + 1] = ss; }
    }
    __syncthreads();
    if (tid < 8) {
        float t = 0.f;
        #pragma unroll
        for (int w = 0; w < 8; w++) t += sred[w*8 + tid];
        atomicAdd(&stats[b*8 + tid], t);
    }
}

// ---------------- mega kernel 1: fps1 (blocks 0-7) || knn1 split-K (8-263) -----
__global__ void __launch_bounds__(256, 2) mega1_kernel(const float* __restrict__ pc,
                                                       int* __restrict__ idx1,
                                                       int* __restrict__ fps1)
{
    extern __shared__ char smem[];
    int blk = blockIdx.x;
    if (blk < 8) {
        fps_dev<4096,1024>(pc + (size_t)blk*3*NPTS, fps1 + (size_t)blk*1024, smem);
    } else {
        int kb = blk - 8;
        int b = kb >> 5, chunk = kb & 31;              // 32 chunks x 128 queries
        knn_split_dev(pc + (size_t)b*3*NPTS, pc + (size_t)b*3*NPTS, NPTS,
                      idx1 + (size_t)b*NPTS*16, chunk*128, smem);
    }
}

// ---------------- fused kernel 2: knn3 (32) || fps2 (8) || edge1_h (2048) ------
__global__ void __launch_bounds__(256) fused2_kernel(const float* __restrict__ qc1,
                                                     const float* __restrict__ feat,
                                                     const int* __restrict__ idx1,
                                                     const float* __restrict__ W1,
                                                     float* __restrict__ h,
                                                     float* __restrict__ stats,
                                                     int* __restrict__ idx3,
                                                     int* __restrict__ fps2)
{
    extern __shared__ char smem[];
    int blk = blockIdx.x;
    if (blk < 32) {
        int b = blk >> 2, chunk = blk & 3;
        knn_dev(qc1 + (size_t)b*3*1024, qc1 + (size_t)b*3*1024, 1024, 1024,
                idx3 + (size_t)b*1024*16, chunk*256, smem);
    } else if (blk < 40) {
        int b = blk - 32;
        fps_dev<1024,256>(qc1 + (size_t)b*3*1024, fps2 + (size_t)b*256, smem);
    } else {
        int e = blk - 40;                 // 0..2047
        int b = e >> 8, qt = e & 255;
        edge_h_dev<8,32>(feat, feat, idx1, W1, h, stats, NPTS, NPTS, b, qt*16, smem);
    }
}

// ---------------- idx2 = idx1[fps1] (knn2 elimination) -------------------------
__global__ void idx2_gather_kernel(const int* __restrict__ idx1, const int* __restrict__ fps1,
                                   int* __restrict__ idx2)
{
    int i = blockIdx.x*256 + threadIdx.x;          // over B*1024*16
    if (i >= BATCH*1024*16) return;
    int s = i & 15; int m = (i >> 4) & 1023; int b = i >> 14;
    idx2[i] = idx1[((size_t)b*NPTS + fps1[b*1024 + m])*16 + s];
}

// ---------------- knn4 (needs gathered out coords) ----------------
__global__ void __launch_bounds__(256) knn4_kernel(const float* __restrict__ qc,
                                                   int* __restrict__ idx4)
{
    extern __shared__ char smem[];
    int b = blockIdx.x;
    knn_dev(qc + (size_t)b*3*256, qc + (size_t)b*3*256, 256, 256,
            idx4 + (size_t)b*256*16, 0, smem);
}

// ---------------- gather: dst[b,c,m] = src[b,c,idx[b,m]] ----------------
__global__ void gather_kernel(const float* __restrict__ src, const int* __restrict__ idx,
                              float* __restrict__ dst, int C, int Nsrc, int M)
{
    int i = blockIdx.x*256 + threadIdx.x;
    if (i >= BATCH*C*M) return;
    int m = i % M; int c = (i/M) % C; int b = i/(M*C);
    dst[i] = src[((size_t)b*C + c)*Nsrc + idx[(size_t)b*M + m]];
}

// ---------------- edge conv wrappers (stages 2,3,4) ----------------
template<int C, int O>
__global__ void edge_h_kernel(const float* __restrict__ kf, const float* __restrict__ qf,
                              const int* __restrict__ idx, const float* __restrict__ W,
                              float* __restrict__ h, float* __restrict__ stats,
                              int Q, int NK)
{
    extern __shared__ char smemc[];
    edge_h_dev<C,O>(kf, qf, idx, W, h, stats, Q, NK, blockIdx.y, blockIdx.x*16, smemc);
}

// ---------------- stats ----------------
__global__ void zero_stats_kernel(float* __restrict__ stats)
{
    int i = threadIdx.x;
    if (i < 64) stats[i] = 0.f;
}
__global__ void stats_fin_kernel(const float* __restrict__ stats, float* __restrict__ musig,
                                 float inv_cnt)
{
    int i = threadIdx.x;
    if (i < 32) {
        float s = stats[i*2], ss = stats[i*2+1];
        float mu  = s * inv_cnt;
        float var = ss * inv_cnt - mu*mu;
        musig[i*2]   = mu;
        musig[i*2+1] = 1.0f / sqrtf(var + 1e-5f);
    }
}

// ---------------- edge conv pass 2: GN + leaky + max over k ----------------
__global__ void edge_out_kernel(const float* __restrict__ h, const float* __restrict__ musig,
                                const float* __restrict__ gamma, const float* __restrict__ beta,
                                float* __restrict__ out, int O, int O4, int Q)
{
    int i = blockIdx.x*256 + threadIdx.x;
    if (i >= BATCH*O*Q) return;
    int o = (i / Q) % O;
    int b = i / (Q*O);
    int g = o / O4;
    float mu   = musig[(b*4+g)*2];
    float rstd = musig[(b*4+g)*2+1];
    float ga = gamma[o], be = beta[o];
    const float4* hp = (const float4*)(h + (size_t)i*16);
    float m = -INFINITY;
    #pragma unroll
    for (int r = 0; r < 4; r++) {
        float4 v = hp[r];
        float vv[4] = {v.x, v.y, v.z, v.w};
        #pragma unroll
        for (int c = 0; c < 4; c++) {
            float xn = (vv[c] - mu) * rstd;
            float y  = xn * ga + be;
            y = (y >= 0.f) ? y : 0.2f * y;
            m = fmaxf(m, y);
        }
    }
    out[i] = m;
}

// ---------------- host orchestration ----------------
static inline int eh_smem(int C, int O) { return (O*2*C + 16*C + 16*O + 64) * 4; }
#define KNN_SMEM 49152

extern "C" void kernel_launch(void* const* d_in, const int* in_sizes, int n_in,
                              void* d_out, int out_size)
{
    const float* pc = (const float*)d_in[0];
    const float* Wt = (const float*)d_in[1];
    const float* bt = (const float*)d_in[2];
    const float* W1 = (const float*)d_in[3];
    const float* g1 = (const float*)d_in[4];
    const float* b1 = (const float*)d_in[5];
    const float* W2 = (const float*)d_in[6];
    const float* g2 = (const float*)d_in[7];
    const float* b2 = (const float*)d_in[8];
    const float* W3 = (const float*)d_in[9];
    const float* g3 = (const float*)d_in[10];
    const float* b3 = (const float*)d_in[11];
    const float* W4 = (const float*)d_in[12];
    const float* g4 = (const float*)d_in[13];
    const float* b4 = (const float*)d_in[14];
    float* out = (float*)d_out;

    float *feat, *h, *kf1, *qc1, *qf1, *qf2, *kf3, *qf4, *stats, *musig;
    int *idx1, *idx2, *idx3, *idx4, *fps1, *fps2;
    cudaGetSymbolAddress((void**)&feat,  g_feat);
    cudaGetSymbolAddress((void**)&h,     g_h);
    cudaGetSymbolAddress((void**)&kf1,   g_kf1);
    cudaGetSymbolAddress((void**)&qc1,   g_qc1);
    cudaGetSymbolAddress((void**)&qf1,   g_qf1);
    cudaGetSymbolAddress((void**)&qf2,   g_qf2);
    cudaGetSymbolAddress((void**)&kf3,   g_kf3);
    cudaGetSymbolAddress((void**)&qf4,   g_qf4);
    cudaGetSymbolAddress((void**)&stats, g_stats);
    cudaGetSymbolAddress((void**)&musig, g_musig);
    cudaGetSymbolAddress((void**)&idx1,  g_idx1);
    cudaGetSymbolAddress((void**)&idx2,  g_idx2);
    cudaGetSymbolAddress((void**)&idx3,  g_idx3);
    cudaGetSymbolAddress((void**)&idx4,  g_idx4);
    cudaGetSymbolAddress((void**)&fps1,  g_fps1);
    cudaGetSymbolAddress((void**)&fps2,  g_fps2);

    cudaFuncSetAttribute(edge_h_kernel<64,128>,
                         cudaFuncAttributeMaxDynamicSharedMemorySize, eh_smem(64,128));

    // launches 1-3 (pads mega1 into the ncu capture slot)
    transform_kernel<<<(BATCH*8*NPTS+255)/256, 256>>>(pc, Wt, bt, feat);
    zero_stats_kernel<<<1,64>>>(stats);
    zero_stats_kernel<<<1,64>>>(stats);

    // launch #4: mega1 = fps1 (8) || knn1 split-K (256)
    mega1_kernel<<<264, 256, KNN_SMEM>>>(pc, idx1, fps1);

    // qc1 gather (only fps1-dependent; unblocks fused2)
    gather_kernel<<<(BATCH*3*1024+255)/256, 256>>>(pc, fps1, qc1, 3, NPTS, 1024);

    // fused2: knn3 (32) || fps2 (8) || edge1_h (2048)
    fused2_kernel<<<2088, 256, KNN_SMEM>>>(qc1, feat, idx1, W1, h, stats, idx3, fps2);

    // idx2 = idx1[fps1]  (knn2 eliminated)
    idx2_gather_kernel<<<(BATCH*1024*16+255)/256, 256>>>(idx1, fps1, idx2);

    // edge_conv 1 epilogue
    stats_fin_kernel<<<1,32>>>(stats, musig, 1.0f/524288.0f);
    edge_out_kernel<<<(BATCH*32*NPTS+255)/256, 256>>>(h, musig, g1, b1, kf1, 32, 8, NPTS);
    gather_kernel<<<(BATCH*32*1024+255)/256,256>>>(kf1, fps1, qf1, 32, NPTS, 1024);

    // edge_conv 2: C=32 -> O=64 (idx2, keys = full 4096 set)
    zero_stats_kernel<<<1,64>>>(stats);
    edge_h_kernel<32,64><<<dim3(1024/16, BATCH), 256, eh_smem(32,64)>>>(kf1, qf1, idx2, W2, h, stats, 1024, NPTS);
    stats_fin_kernel<<<1,32>>>(stats, musig, 1.0f/262144.0f);
    edge_out_kernel<<<(BATCH*64*1024+255)/256, 256>>>(h, musig, g2, b2, qf2, 64, 16, 1024);

    // edge_conv 3: C=64 -> O=64 (idx3 from fused2)
    zero_stats_kernel<<<1,64>>>(stats);
    edge_h_kernel<64,64><<<dim3(1024/16, BATCH), 256, eh_smem(64,64)>>>(qf2, qf2, idx3, W3, h, stats, 1024, 1024);
    stats_fin_kernel<<<1,32>>>(stats, musig, 1.0f/262144.0f);
    edge_out_kernel<<<(BATCH*64*1024+255)/256, 256>>>(h, musig, g3, b3, kf3, 64, 16, 1024);

    // fps2 gathers (coords straight into d_out) + knn4
    gather_kernel<<<(BATCH*3*256+255)/256, 256>>>(qc1, fps2, out, 3, 1024, 256);
    gather_kernel<<<(BATCH*64*256+255)/256,256>>>(kf3, fps2, qf4, 64, 1024, 256);
    knn4_kernel<<<8, 256, KNN_SMEM>>>(out, idx4);

    // edge_conv 4: C=64 -> O=128
    zero_stats_kernel<<<1,64>>>(stats);
    edge_h_kernel<64,128><<<dim3(256/16, BATCH), 256, eh_smem(64,128)>>>(qf4, qf4, idx4, W4, h, stats, 256, 256);
    stats_fin_kernel<<<1,32>>>(stats, musig, 1.0f/131072.0f);
    edge_out_kernel<<<(BATCH*128*256+255)/256, 256>>>(h, musig, g4, b4, out + BATCH*3*256, 128, 32, 256);
}

// round 11
// speedup vs baseline: 1.1921x; 1.0097x over previous
#include <cuda_runtime.h>
#include <cstdint>
#include <math.h>

#define BATCH 8
#define NPTS 4096

// ---------------- scratch (static device globals; no allocation) ----------------
__device__ float g_feat[BATCH*8*NPTS];
__device__ float g_h   [BATCH*32*NPTS*16];      // reused by all stages
__device__ float g_kf1 [BATCH*32*NPTS];
__device__ float g_qc1 [BATCH*3*1024];
__device__ float g_qf2 [BATCH*64*1024];
__device__ float g_kf3 [BATCH*64*1024];
__device__ int   g_idx1[BATCH*NPTS*16];
__device__ int   g_idx2[BATCH*1024*16];
__device__ int   g_idx3[BATCH*1024*16];
__device__ int   g_idx4[BATCH*256*16];
__device__ int   g_fps1[BATCH*1024];
__device__ int   g_fps2[BATCH*256];
__device__ float g_stats[256];                  // 4 stages x 64
__device__ float g_musig[64];                   // pad-kernel target (unused data)

// ---------------- f32x2 packed helpers (used ONLY in fps, validated lineage) ---
__device__ __forceinline__ unsigned long long pk2(float a, float b) {
    unsigned long long r; asm("mov.b64 %0,{%1,%2};" : "=l"(r) : "f"(a), "f"(b)); return r;
}
__device__ __forceinline__ void upk2(unsigned long long v, float& a, float& b) {
    asm("mov.b64 {%0,%1},%2;" : "=f"(a), "=f"(b) : "l"(v));
}
__device__ __forceinline__ unsigned long long addx2(unsigned long long a, unsigned long long b) {
    unsigned long long r; asm("add.rn.f32x2 %0,%1,%2;" : "=l"(r) : "l"(a), "l"(b)); return r;
}
__device__ __forceinline__ unsigned long long mulx2(unsigned long long a, unsigned long long b) {
    unsigned long long r; asm("mul.rn.f32x2 %0,%1,%2;" : "=l"(r) : "l"(a), "l"(b)); return r;
}

// ---------------- transform: feat = Wt @ pc + bt ; block 0 zeros stats ---------
__global__ void transform_kernel(const float* __restrict__ pc, const float* __restrict__ Wt,
                                 const float* __restrict__ bt, float* __restrict__ feat,
                                 float* __restrict__ stats)
{
    int i = blockIdx.x*256 + threadIdx.x;
    if (blockIdx.x == 0) stats[threadIdx.x] = 0.f;   // 4 stages x 64
    if (i >= BATCH*8*NPTS) return;
    int n = i & (NPTS-1);
    int o = (i >> 12) & 7;
    int b = i >> 15;
    const float* p = pc + (size_t)b*3*NPTS;
    float v = Wt[o*3+0]*p[n] + Wt[o*3+1]*p[NPTS+n] + Wt[o*3+2]*p[2*NPTS+n] + bt[o];
    feat[i] = v;
}

// ---------------- pad kernel (keeps mega1 in the ncu capture slot) -------------
__global__ void pad_kernel(float* __restrict__ musig)
{
    int i = threadIdx.x;
    if (i < 64) musig[i] = 0.f;
}

// ---------------- knn insert: group-max cached, O(4) rescan --------------------
__device__ __forceinline__ void knn_insert_grp(unsigned skeybase,
        unsigned long long (*skey)[256], int tid, bool acc, unsigned long long key,
        unsigned long long* gmax, int* gslot,
        unsigned long long& worst, int& wslot, float& worstf)
{
    unsigned saddr = skeybase + (unsigned)(wslot*2048 + tid*8);
    asm volatile("{\n .reg .pred p;\n setp.ne.u32 p, %0, 0;\n @p st.shared.b64 [%1], %2;\n}"
                 :: "r"((int)acc), "r"(saddr), "l"(key) : "memory");
    const int g = wslot >> 2;
    unsigned long long a = skey[(g<<2)+0][tid];
    unsigned long long b = skey[(g<<2)+1][tid];
    unsigned long long c = skey[(g<<2)+2][tid];
    unsigned long long d = skey[(g<<2)+3][tid];
    bool p1 = b > a; unsigned long long m1 = p1?b:a; int s1 = (g<<2)|(int)p1;
    bool p2 = d > c; unsigned long long m2 = p2?d:c; int s2 = (g<<2)|2|(int)p2;
    bool pf = m2 > m1; unsigned long long ng = pf?m2:m1; int ns = pf?s2:s1;
    #pragma unroll
    for (int s = 0; s < 4; s++) {
        bool pe = (g == s);
        gmax[s]  = pe ? ng : gmax[s];
        gslot[s] = pe ? ns : gslot[s];
    }
    bool q1 = gmax[1] > gmax[0]; unsigned long long w1 = q1?gmax[1]:gmax[0]; int u1 = q1?gslot[1]:gslot[0];
    bool q2 = gmax[3] > gmax[2]; unsigned long long w2 = q2?gmax[3]:gmax[2]; int u2 = q2?gslot[3]:gslot[2];
    bool qf = w2 > w1; worst = qf?w2:w1; wslot = qf?u2:u1;
    if (worst == 0xFFFFFFFFFFFFFFFFULL) {
        worstf = __int_as_float(0x7f800000);
    } else {
        unsigned m = (unsigned)(worst >> 32);
        unsigned orig = (m & 0x80000000u) ? (m ^ 0x80000000u) : ~m;
        worstf = __uint_as_float(orig);
    }
}

// ---------------- knn device fn (full scan; knn3/knn4) -------------------------
__device__ void knn_dev(const float* __restrict__ qb, const float* __restrict__ kb,
                        int Q, int NK, int* __restrict__ out, int qbase, char* smemraw)
{
    float4* tile = (float4*)smemraw;
    unsigned long long (*skey)[256] = (unsigned long long (*)[256])(smemraw + 16384);
    const int tid = threadIdx.x;
    const int q = qbase + tid;
    unsigned skeybase = (unsigned)__cvta_generic_to_shared(&skey[0][0]);

    float qx = qb[q], qy = qb[Q+q], qz = qb[2*Q+q];
    float q2 = __fadd_rn(__fadd_rn(__fmul_rn(qx,qx), __fmul_rn(qy,qy)), __fmul_rn(qz,qz));

    #pragma unroll
    for (int s = 0; s < 16; s++) skey[s][tid] = 0xFFFFFFFFFFFFFFFFULL;
    unsigned long long gmax[4]; int gslot[4];
    #pragma unroll
    for (int s = 0; s < 4; s++) { gmax[s] = 0xFFFFFFFFFFFFFFFFULL; gslot[s] = s<<2; }
    unsigned long long worst = 0xFFFFFFFFFFFFFFFFULL;
    float worstf = __int_as_float(0x7f800000);
    int wslot = 0;

    for (int t0 = 0; t0 < NK; t0 += 1024) {
        int tn = min(1024, NK - t0);
        __syncthreads();
        for (int i = tid; i < tn; i += 256) {
            float kx = kb[t0+i], ky = kb[NK+t0+i], kz = kb[2*NK+t0+i];
            float k2 = __fadd_rn(__fadd_rn(__fmul_rn(kx,kx), __fmul_rn(ky,ky)), __fmul_rn(kz,kz));
            tile[i] = make_float4(kx, ky, kz, k2);
        }
        __syncthreads();
        #pragma unroll 2
        for (int j = 0; j < tn; j++) {
            float4 kv = tile[j];
            float dt = __fadd_rn(__fadd_rn(__fmul_rn(qx,kv.x), __fmul_rn(qy,kv.y)), __fmul_rn(qz,kv.z));
            float d2 = __fsub_rn(__fadd_rn(q2, kv.w), __fmul_rn(2.0f, dt));
            bool acc = d2 < worstf;    // strict: equal-d2 at larger idx loses anyway
            if (__any_sync(0xFFFFFFFFu, acc)) {
                unsigned ub = __float_as_uint(d2);
                ub ^= ((int)ub < 0) ? 0xFFFFFFFFu : 0x80000000u;
                unsigned long long key = ((unsigned long long)ub << 32) | (unsigned)(t0 + j);
                knn_insert_grp(skeybase, skey, tid, acc, key, gmax, gslot, worst, wslot, worstf);
            }
        }
    }
    #pragma unroll
    for (int s = 0; s < 16; s++)
        out[(size_t)q*16 + s] = (int)(skey[s][tid] & 0xFFFFFFFFu);
}

// ---------------- knn split-K device fn (knn1) ---------------------------------
__device__ void knn_split_dev(const float* __restrict__ qb, const float* __restrict__ kb,
                              int NK, int* __restrict__ out, int qbase, char* smemraw)
{
    float4* tile = (float4*)smemraw;
    unsigned long long (*skey)[256] = (unsigned long long (*)[256])(smemraw + 16384);
    const int tid = threadIdx.x;
    const int ql  = tid & 127;
    const int par = tid >> 7;
    const int q   = qbase + ql;
    unsigned skeybase = (unsigned)__cvta_generic_to_shared(&skey[0][0]);

    float qx = qb[q], qy = qb[NK+q], qz = qb[2*NK+q];   // Q == NK (self)
    float q2 = __fadd_rn(__fadd_rn(__fmul_rn(qx,qx), __fmul_rn(qy,qy)), __fmul_rn(qz,qz));

    #pragma unroll
    for (int s = 0; s < 16; s++) skey[s][tid] = 0xFFFFFFFFFFFFFFFFULL;
    unsigned long long gmax[4]; int gslot[4];
    #pragma unroll
    for (int s = 0; s < 4; s++) { gmax[s] = 0xFFFFFFFFFFFFFFFFULL; gslot[s] = s<<2; }
    unsigned long long worst = 0xFFFFFFFFFFFFFFFFULL;
    float worstf = __int_as_float(0x7f800000);
    int wslot = 0;

    for (int t0 = 0; t0 < NK; t0 += 1024) {
        __syncthreads();
        for (int i = tid; i < 1024; i += 256) {
            float kx = kb[t0+i], ky = kb[NK+t0+i], kz = kb[2*NK+t0+i];
            float k2 = __fadd_rn(__fadd_rn(__fmul_rn(kx,kx), __fmul_rn(ky,ky)), __fmul_rn(kz,kz));
            tile[i] = make_float4(kx, ky, kz, k2);
        }
        __syncthreads();
        #pragma unroll 2
        for (int i = 0; i < 512; i++) {
            int j = (i << 1) | par;
            float4 kv = tile[j];
            float dt = __fadd_rn(__fadd_rn(__fmul_rn(qx,kv.x), __fmul_rn(qy,kv.y)), __fmul_rn(qz,kv.z));
            float d2 = __fsub_rn(__fadd_rn(q2, kv.w), __fmul_rn(2.0f, dt));
            bool acc = d2 < worstf;
            if (__any_sync(0xFFFFFFFFu, acc)) {
                unsigned ub = __float_as_uint(d2);
                ub ^= ((int)ub < 0) ? 0xFFFFFFFFu : 0x80000000u;
                unsigned long long key = ((unsigned long long)ub << 32) | (unsigned)(t0 + j);
                knn_insert_grp(skeybase, skey, tid, acc, key, gmax, gslot, worst, wslot, worstf);
            }
        }
    }
    __syncthreads();
    if (tid < 128) {
        for (int r = 0; r < 16; r++) {
            unsigned long long best = 0xFFFFFFFFFFFFFFFFULL; int bs = 0;
            #pragma unroll
            for (int s = 0; s < 32; s++) {
                unsigned long long vv = (s < 16) ? skey[s][tid] : skey[s-16][tid+128];
                if (vv < best) { best = vv; bs = s; }
            }
            out[(size_t)q*16 + r] = (int)(best & 0xFFFFFFFFu);
            if (bs < 16) skey[bs][tid] = 0xFFFFFFFFFFFFFFFFULL;
            else         skey[bs-16][tid+128] = 0xFFFFFFFFFFFFFFFFULL;
        }
    }
}

// ---------------- FPS device fn (+ coordinate gather epilogue) -----------------
// After selection, the block gathers coords itself: gout[c*M+m] = cb[c*NP+outi[m]].
template<int NP, int M>
__device__ void fps_dev(const float* __restrict__ cb, int* __restrict__ outi,
                        float* __restrict__ gout, char* smemraw)
{
    constexpr int PPT = NP / 256;
    constexpr int PAIRS = PPT / 2;
    static_assert(PPT * 256 == NP && PAIRS * 2 == PPT, "layout");
    const int tid  = threadIdx.x;
    const int warp = tid >> 5;
    unsigned long long (*skeys)[8] = (unsigned long long (*)[8])smemraw;   // [2][8]

    unsigned long long xp[PAIRS], yp[PAIRS], zp[PAIRS];
    float d_[PPT];
    #pragma unroll
    for (int pr = 0; pr < PAIRS; pr++) {
        int i0 = (2*pr)*256 + tid, i1 = (2*pr+1)*256 + tid;
        xp[pr] = pk2(cb[i0],        cb[i1]);
        yp[pr] = pk2(cb[NP+i0],     cb[NP+i1]);
        zp[pr] = pk2(cb[2*NP+i0],   cb[2*NP+i1]);
        d_[2*pr] = 1e10f; d_[2*pr+1] = 1e10f;
    }
    if (tid == 0) outi[0] = 0;

    int last = 0;
    for (int t = 1; t < M; t++) {
        float px = __ldg(cb + last), py = __ldg(cb + NP + last), pz = __ldg(cb + 2*NP + last);
        unsigned long long pxn = pk2(-px, -px), pyn = pk2(-py, -py), pzn = pk2(-pz, -pz);
        float bestd = -1.0f; int besti = 0;
        #pragma unroll
        for (int pr = 0; pr < PAIRS; pr++) {
            // exact reference sequence per lane: sub, 3x mul, 2x add (NO fma)
            unsigned long long dx = addx2(xp[pr], pxn);
            unsigned long long dy = addx2(yp[pr], pyn);
            unsigned long long dz = addx2(zp[pr], pzn);
            unsigned long long s2 = addx2(addx2(mulx2(dx,dx), mulx2(dy,dy)), mulx2(dz,dz));
            float m0, m1; upk2(s2, m0, m1);
            float d0 = fminf(d_[2*pr],   m0); d_[2*pr]   = d0;
            float d1 = fminf(d_[2*pr+1], m1); d_[2*pr+1] = d1;
            if (d0 > bestd) { bestd = d0; besti = (2*pr)*256 + tid; }
            if (d1 > bestd) { bestd = d1; besti = (2*pr+1)*256 + tid; }
        }
        unsigned db     = __float_as_uint(bestd);          // d >= 0 so bits ordered
        unsigned rmax   = __reduce_max_sync(0xFFFFFFFFu, db);
        unsigned inv    = (db == rmax) ? (0xFFFFFFFFu - (unsigned)besti) : 0u;
        unsigned invmax = __reduce_max_sync(0xFFFFFFFFu, inv);
        if ((tid & 31) == 0)
            skeys[t & 1][warp] = ((unsigned long long)rmax << 32) | invmax;
        __syncthreads();
        const unsigned long long* kk = skeys[t & 1];
        unsigned long long k0 = kk[0] > kk[1] ? kk[0] : kk[1];
        unsigned long long k1 = kk[2] > kk[3] ? kk[2] : kk[3];
        unsigned long long k2 = kk[4] > kk[5] ? kk[4] : kk[5];
        unsigned long long k3 = kk[6] > kk[7] ? kk[6] : kk[7];
        k0 = k0 > k1 ? k0 : k1;
        k2 = k2 > k3 ? k2 : k3;
        k0 = k0 > k2 ? k0 : k2;
        last = (int)(0xFFFFFFFFu - (unsigned)(k0 & 0xFFFFFFFFu));
        if (tid == 0) outi[t] = last;
    }
    __syncthreads();                      // outi writes (tid 0) visible block-wide
    for (int e = tid; e < 3*M; e += 256) {
        int c = e / M, m = e - c*M;
        gout[e] = cb[c*NP + outi[m]];
    }
}

// ---------------- edge conv pass 1 (generalized with query/neighbor remaps) ----
template<int C, int O>
__device__ void edge_h_dev(const float* __restrict__ kf, int nkstride,
                           const float* __restrict__ qf, int qstride,
                           const int* __restrict__ qmap, const int* __restrict__ nmap,
                           const int* __restrict__ idx, int Q,
                           const float* __restrict__ W,
                           float* __restrict__ h, float* __restrict__ stats,
                           int b, int qbase, char* smemraw)
{
    float* sW   = (float*)smemraw;      // O*2C
    float* sqf  = sW  + O*2*C;          // [c*16+ql]
    float* sqb  = sqf + C*16;           // [ql*O+o]
    float* sred = sqb + 16*O;           // 8 warps * 8

    const int tid = threadIdx.x;

    for (int i = tid; i < O*2*C; i += 256) sW[i] = W[i];
    for (int i = tid; i < C*16;  i += 256) {
        int qi = qbase + (i & 15);
        int col = qmap ? qmap[qi] : qi;
        sqf[i] = qf[((size_t)b*C + (i >> 4))*qstride + col];
    }
    __syncthreads();

    for (int e = tid; e < 16*O; e += 256) {
        int ql = e / O, o = e - ql*O;
        float acc = 0.f;
        #pragma unroll
        for (int c = 0; c < C; c++) acc = fmaf(sW[o*2*C + C + c], sqf[c*16 + ql], acc);
        sqb[e] = acc;
    }
    __syncthreads();

    const int ql = tid >> 4, k = tid & 15;
    const int q = qbase + ql;
    int j = idx[((size_t)b*Q + q)*16 + k];
    if (nmap) j = nmap[j];

    float e_[C];
    #pragma unroll
    for (int c = 0; c < C; c++)
        e_[c] = kf[((size_t)b*C + c)*nkstride + j] - sqf[c*16 + ql];

    float* hp = h + ((size_t)b*O*Q + q)*16 + k;
    const float* sqbp = sqb + ql*O;
    const int lane = tid & 31, warp = tid >> 5;

    #pragma unroll
    for (int g = 0; g < 4; g++) {
        float s = 0.f, ss = 0.f;
        for (int o = g*(O/4); o < (g+1)*(O/4); o++) {
            float acc = sqbp[o];
            const float* wr = sW + o*2*C;
            #pragma unroll
            for (int c = 0; c < C; c++) acc = fmaf(wr[c], e_[c], acc);
            hp[(size_t)o*Q*16] = acc;
            s += acc; ss = fmaf(acc, acc, ss);
        }
        #pragma unroll
        for (int off = 16; off; off >>= 1) {
            s  += __shfl_xor_sync(0xFFFFFFFFu, s,  off);
            ss += __shfl_xor_sync(0xFFFFFFFFu, ss, off);
        }
        if (lane == 0) { sred[warp*8 + g*2] = s; sred[warp*8 + g*2 + 1] = ss; }
    }
    __syncthreads();
    if (tid < 8) {
        float t = 0.f;
        #pragma unroll
        for (int w = 0; w < 8; w++) t += sred[w*8 + tid];
        atomicAdd(&stats[b*8 + tid], t);
    }
}

// ---------------- edge conv pass 2: inline GN stats + leaky + max over k -------
__device__ __forceinline__ void edge_out_dev(const float* __restrict__ h,
        const float* __restrict__ stats, float inv_cnt,
        const float* __restrict__ gamma, const float* __restrict__ beta,
        float* __restrict__ out, int O, int O4, int Q, int i)
{
    if (i >= BATCH*O*Q) return;
    int o = (i / Q) % O;
    int b = i / (Q*O);
    int g = o / O4;
    float s  = stats[b*8 + g*2];
    float ss = stats[b*8 + g*2 + 1];
    float mu  = s * inv_cnt;
    float var = ss * inv_cnt - mu*mu;
    float rstd = 1.0f / sqrtf(var + 1e-5f);
    float ga = gamma[o], be = beta[o];
    const float4* hp = (const float4*)(h + (size_t)i*16);
    float m = -INFINITY;
    #pragma unroll
    for (int r = 0; r < 4; r++) {
        float4 v = hp[r];
        float vv[4] = {v.x, v.y, v.z, v.w};
        #pragma unroll
        for (int c = 0; c < 4; c++) {
            float xn = (vv[c] - mu) * rstd;
            float y  = xn * ga + be;
            y = (y >= 0.f) ? y : 0.2f * y;
            m = fmaxf(m, y);
        }
    }
    out[i] = m;
}

__global__ void edge_out_kernel(const float* __restrict__ h, const float* __restrict__ stats,
                                float inv_cnt, const float* __restrict__ gamma,
                                const float* __restrict__ beta, float* __restrict__ out,
                                int O, int O4, int Q)
{
    edge_out_dev(h, stats, inv_cnt, gamma, beta, out, O, O4, Q, blockIdx.x*256 + threadIdx.x);
}

// ---------------- mega kernel 1: fps1 (0-7, writes qc1) || knn1 split (8-263) --
__global__ void __launch_bounds__(256, 2) mega1_kernel(const float* __restrict__ pc,
                                                       int* __restrict__ idx1,
                                                       int* __restrict__ fps1,
                                                       float* __restrict__ qc1)
{
    extern __shared__ char smem[];
    int blk = blockIdx.x;
    if (blk < 8) {
        fps_dev<4096,1024>(pc + (size_t)blk*3*NPTS, fps1 + (size_t)blk*1024,
                           qc1 + (size_t)blk*3*1024, smem);
    } else {
        int kb = blk - 8;
        int b = kb >> 5, chunk = kb & 31;
        knn_split_dev(pc + (size_t)b*3*NPTS, pc + (size_t)b*3*NPTS, NPTS,
                      idx1 + (size_t)b*NPTS*16, chunk*128, smem);
    }
}

// ---------------- fused kernel 2: knn3 (32) || fps2 (8, writes out coords) || edge1_h
__global__ void __launch_bounds__(256) fused2_kernel(const float* __restrict__ qc1,
                                                     const float* __restrict__ feat,
                                                     const int* __restrict__ idx1,
                                                     const float* __restrict__ W1,
                                                     float* __restrict__ h,
                                                     float* __restrict__ stats0,
                                                     int* __restrict__ idx3,
                                                     int* __restrict__ fps2,
                                                     float* __restrict__ out)
{
    extern __shared__ char smem[];
    int blk = blockIdx.x;
    if (blk < 32) {
        int b = blk >> 2, chunk = blk & 3;
        knn_dev(qc1 + (size_t)b*3*1024, qc1 + (size_t)b*3*1024, 1024, 1024,
                idx3 + (size_t)b*1024*16, chunk*256, smem);
    } else if (blk < 40) {
        int b = blk - 32;
        fps_dev<1024,256>(qc1 + (size_t)b*3*1024, fps2 + (size_t)b*256,
                          out + (size_t)b*3*256, smem);
    } else {
        int e = blk - 40;                 // 0..2047
        int b = e >> 8, qt = e & 255;
        edge_h_dev<8,32>(feat, NPTS, feat, NPTS, nullptr, nullptr, idx1, NPTS,
                         W1, h, stats0, b, qt*16, smem);
    }
}

// ---------------- combo5: edge_out1 (4096) + idx2 gather (512) -----------------
__global__ void combo5_kernel(const float* __restrict__ h, const float* __restrict__ stats0,
                              const float* __restrict__ g1, const float* __restrict__ b1,
                              float* __restrict__ kf1,
                              const int* __restrict__ idx1, const int* __restrict__ fps1,
                              int* __restrict__ idx2)
{
    int blk = blockIdx.x;
    if (blk < 4096) {
        edge_out_dev(h, stats0, 1.0f/524288.0f, g1, b1, kf1, 32, 8, NPTS,
                     blk*256 + threadIdx.x);
    } else {
        int i = (blk - 4096)*256 + threadIdx.x;      // over B*1024*16
        if (i < BATCH*1024*16) {
            int s = i & 15; int m = (i >> 4) & 1023; int b = i >> 14;
            idx2[i] = idx1[((size_t)b*NPTS + fps1[b*1024 + m])*16 + s];
        }
    }
}

// ---------------- kernel6: knn4 (0-7, on out coords) || edge_h2 (8-519) --------
__global__ void __launch_bounds__(256) kernel6(const float* __restrict__ out,
                                               int* __restrict__ idx4,
                                               const float* __restrict__ kf1,
                                               const int* __restrict__ fps1,
                                               const int* __restrict__ idx2,
                                               const float* __restrict__ W2,
                                               float* __restrict__ h,
                                               float* __restrict__ stats1)
{
    extern __shared__ char smem[];
    int blk = blockIdx.x;
    if (blk < 8) {
        knn_dev(out + (size_t)blk*3*256, out + (size_t)blk*3*256, 256, 256,
                idx4 + (size_t)blk*256*16, 0, smem);
    } else {
        int e = blk - 8;                  // 0..511
        int b = e >> 6, qt = e & 63;
        edge_h_dev<32,64>(kf1, NPTS, kf1, NPTS, fps1 + b*1024, nullptr, idx2, 1024,
                          W2, h, stats1, b, qt*16, smem);
    }
}

// ---------------- edge_h wrappers (stages 3,4) ---------------------------------
__global__ void edge_h3_kernel(const float* __restrict__ qf2, const int* __restrict__ idx3,
                               const float* __restrict__ W3, float* __restrict__ h,
                               float* __restrict__ stats2)
{
    extern __shared__ char smemc[];
    edge_h_dev<64,64>(qf2, 1024, qf2, 1024, nullptr, nullptr, idx3, 1024,
                      W3, h, stats2, blockIdx.y, blockIdx.x*16, smemc);
}

__global__ void edge_h4_kernel(const float* __restrict__ kf3, const int* __restrict__ fps2,
                               const int* __restrict__ idx4, const float* __restrict__ W4,
                               float* __restrict__ h, float* __restrict__ stats3)
{
    extern __shared__ char smemc[];
    int b = blockIdx.y;
    edge_h_dev<64,128>(kf3, 1024, kf3, 1024, fps2 + b*256, fps2 + b*256, idx4, 256,
                       W4, h, stats3, b, blockIdx.x*16, smemc);
}

// ---------------- host orchestration ----------------
static inline int eh_smem(int C, int O) { return (O*2*C + 16*C + 16*O + 64) * 4; }
#define KNN_SMEM 49152

extern "C" void kernel_launch(void* const* d_in, const int* in_sizes, int n_in,
                              void* d_out, int out_size)
{
    const float* pc = (const float*)d_in[0];
    const float* Wt = (const float*)d_in[1];
    const float* bt = (const float*)d_in[2];
    const float* W1 = (const float*)d_in[3];
    const float* g1 = (const float*)d_in[4];
    const float* b1 = (const float*)d_in[5];
    const float* W2 = (const float*)d_in[6];
    const float* g2 = (const float*)d_in[7];
    const float* b2 = (const float*)d_in[8];
    const float* W3 = (const float*)d_in[9];
    const float* g3 = (const float*)d_in[10];
    const float* b3 = (const float*)d_in[11];
    const float* W4 = (const float*)d_in[12];
    const float* g4 = (const float*)d_in[13];
    const float* b4 = (const float*)d_in[14];
    float* out = (float*)d_out;

    float *feat, *h, *kf1, *qc1, *qf2, *kf3, *stats, *musig;
    int *idx1, *idx2, *idx3, *idx4, *fps1, *fps2;
    cudaGetSymbolAddress((void**)&feat,  g_feat);
    cudaGetSymbolAddress((void**)&h,     g_h);
    cudaGetSymbolAddress((void**)&kf1,   g_kf1);
    cudaGetSymbolAddress((void**)&qc1,   g_qc1);
    cudaGetSymbolAddress((void**)&qf2,   g_qf2);
    cudaGetSymbolAddress((void**)&kf3,   g_kf3);
    cudaGetSymbolAddress((void**)&stats, g_stats);
    cudaGetSymbolAddress((void**)&musig, g_musig);
    cudaGetSymbolAddress((void**)&idx1,  g_idx1);
    cudaGetSymbolAddress((void**)&idx2,  g_idx2);
    cudaGetSymbolAddress((void**)&idx3,  g_idx3);
    cudaGetSymbolAddress((void**)&idx4,  g_idx4);
    cudaGetSymbolAddress((void**)&fps1,  g_fps1);
    cudaGetSymbolAddress((void**)&fps2,  g_fps2);

    float* st0 = stats;          // stage 1
    float* st1 = stats + 64;     // stage 2
    float* st2 = stats + 128;    // stage 3
    float* st3 = stats + 192;    // stage 4

    cudaFuncSetAttribute(edge_h4_kernel,
                         cudaFuncAttributeMaxDynamicSharedMemorySize, eh_smem(64,128));

    // 1: transform + stats zero
    transform_kernel<<<(BATCH*8*NPTS+255)/256, 256>>>(pc, Wt, bt, feat, stats);
    // 2-3: pads (keep mega1 in the ncu capture slot)
    pad_kernel<<<1,64>>>(musig);
    pad_kernel<<<1,64>>>(musig);

    // 4: mega1 = fps1 (writes qc1) || knn1 split-K
    mega1_kernel<<<264, 256, KNN_SMEM>>>(pc, idx1, fps1, qc1);

    // 5: fused2 = knn3 || fps2 (writes out coords) || edge1_h
    fused2_kernel<<<2088, 256, KNN_SMEM>>>(qc1, feat, idx1, W1, h, st0, idx3, fps2, out);

    // 6: edge_out1 (-> kf1) + idx2 = idx1[fps1]
    combo5_kernel<<<4608, 256>>>(h, st0, g1, b1, kf1, idx1, fps1, idx2);

    // 7: knn4 (on out coords) + edge_h2 (queries remapped via fps1, no qf1 array)
    kernel6<<<520, 256, KNN_SMEM>>>(out, idx4, kf1, fps1, idx2, W2, h, st1);

    // 8: edge_out2 -> qf2
    edge_out_kernel<<<(BATCH*64*1024+255)/256, 256>>>(h, st1, 1.0f/262144.0f, g2, b2, qf2, 64, 16, 1024);

    // 9: edge_h3
    edge_h3_kernel<<<dim3(64, BATCH), 256, eh_smem(64,64)>>>(qf2, idx3, W3, h, st2);

    // 10: edge_out3 -> kf3
    edge_out_kernel<<<(BATCH*64*1024+255)/256, 256>>>(h, st2, 1.0f/262144.0f, g3, b3, kf3, 64, 16, 1024);

    // 11: edge_h4 (queries+neighbors remapped via fps2, no qf4 array)
    edge_h4_kernel<<<dim3(16, BATCH), 256, eh_smem(64,128)>>>(kf3, fps2, idx4, W4, h, st3);

    // 12: edge_out4 -> out features
    edge_out_kernel<<<(BATCH*128*256+255)/256, 256>>>(h, st3, 1.0f/131072.0f, g4, b4,
                                                      out + BATCH*3*256, 128, 32, 256);
}

// round 12
// speedup vs baseline: 1.3418x; 1.1255x over previous
#include <cuda_runtime.h>
#include <cstdint>
#include <math.h>

#define BATCH 8
#define NPTS 4096

// ---------------- scratch (static device globals; no allocation) ----------------
__device__ float g_feat[BATCH*8*NPTS];
__device__ float g_h   [BATCH*32*NPTS*16];      // reused by all stages
__device__ float g_kf1 [BATCH*32*NPTS];
__device__ float g_qc1 [BATCH*3*1024];
__device__ float g_qf2 [BATCH*64*1024];
__device__ float g_kf3 [BATCH*64*1024];
__device__ int   g_idx1[BATCH*NPTS*16];
__device__ int   g_idx2[BATCH*1024*16];
__device__ int   g_idx3[BATCH*1024*16];
__device__ int   g_idx4[BATCH*256*16];
__device__ int   g_fps1[BATCH*1024];
__device__ int   g_fps2[BATCH*256];
__device__ float g_stats[256];                  // 4 stages x 64
__device__ float g_musig[64];                   // pad-kernel target (unused data)

// ---------------- f32x2 packed helpers (fps only, validated lineage) -----------
__device__ __forceinline__ unsigned long long pk2(float a, float b) {
    unsigned long long r; asm("mov.b64 %0,{%1,%2};" : "=l"(r) : "f"(a), "f"(b)); return r;
}
__device__ __forceinline__ void upk2(unsigned long long v, float& a, float& b) {
    asm("mov.b64 {%0,%1},%2;" : "=f"(a), "=f"(b) : "l"(v));
}
__device__ __forceinline__ unsigned long long addx2(unsigned long long a, unsigned long long b) {
    unsigned long long r; asm("add.rn.f32x2 %0,%1,%2;" : "=l"(r) : "l"(a), "l"(b)); return r;
}
__device__ __forceinline__ unsigned long long mulx2(unsigned long long a, unsigned long long b) {
    unsigned long long r; asm("mul.rn.f32x2 %0,%1,%2;" : "=l"(r) : "l"(a), "l"(b)); return r;
}

// ---------------- transform: feat = Wt @ pc + bt ; block 0 zeros stats ---------
__global__ void transform_kernel(const float* __restrict__ pc, const float* __restrict__ Wt,
                                 const float* __restrict__ bt, float* __restrict__ feat,
                                 float* __restrict__ stats)
{
    int i = blockIdx.x*256 + threadIdx.x;
    if (blockIdx.x == 0) stats[threadIdx.x] = 0.f;   // 4 stages x 64
    if (i >= BATCH*8*NPTS) return;
    int n = i & (NPTS-1);
    int o = (i >> 12) & 7;
    int b = i >> 15;
    const float* p = pc + (size_t)b*3*NPTS;
    float v = Wt[o*3+0]*p[n] + Wt[o*3+1]*p[NPTS+n] + Wt[o*3+2]*p[2*NPTS+n] + bt[o];
    feat[i] = v;
}

// ---------------- pad kernel (keeps mega1 in the ncu capture slot) -------------
__global__ void pad_kernel(float* __restrict__ musig)
{
    int i = threadIdx.x;
    if (i < 64) musig[i] = 0.f;
}

// ---------------- knn distance (exact reference rn sequence) -------------------
__device__ __forceinline__ float knn_d2(float qx, float qy, float qz, float q2, float4 kv)
{
    float dt = __fadd_rn(__fadd_rn(__fmul_rn(qx,kv.x), __fmul_rn(qy,kv.y)), __fmul_rn(qz,kv.z));
    return __fsub_rn(__fadd_rn(q2, kv.w), __fmul_rn(2.0f, dt));
}

// ---------------- knn insert: group-max cached, O(4) rescan --------------------
__device__ __forceinline__ void knn_insert_grp(unsigned skeybase,
        unsigned long long (*skey)[256], int tid, bool acc, unsigned long long key,
        unsigned long long* gmax, int* gslot,
        unsigned long long& worst, int& wslot, float& worstf)
{
    unsigned saddr = skeybase + (unsigned)(wslot*2048 + tid*8);
    asm volatile("{\n .reg .pred p;\n setp.ne.u32 p, %0, 0;\n @p st.shared.b64 [%1], %2;\n}"
                 :: "r"((int)acc), "r"(saddr), "l"(key) : "memory");
    const int g = wslot >> 2;
    unsigned long long a = skey[(g<<2)+0][tid];
    unsigned long long b = skey[(g<<2)+1][tid];
    unsigned long long c = skey[(g<<2)+2][tid];
    unsigned long long d = skey[(g<<2)+3][tid];
    bool p1 = b > a; unsigned long long m1 = p1?b:a; int s1 = (g<<2)|(int)p1;
    bool p2 = d > c; unsigned long long m2 = p2?d:c; int s2 = (g<<2)|2|(int)p2;
    bool pf = m2 > m1; unsigned long long ng = pf?m2:m1; int ns = pf?s2:s1;
    #pragma unroll
    for (int s = 0; s < 4; s++) {
        bool pe = (g == s);
        gmax[s]  = pe ? ng : gmax[s];
        gslot[s] = pe ? ns : gslot[s];
    }
    bool q1 = gmax[1] > gmax[0]; unsigned long long w1 = q1?gmax[1]:gmax[0]; int u1 = q1?gslot[1]:gslot[0];
    bool q2 = gmax[3] > gmax[2]; unsigned long long w2 = q2?gmax[3]:gmax[2]; int u2 = q2?gslot[3]:gslot[2];
    bool qf = w2 > w1; worst = qf?w2:w1; wslot = qf?u2:u1;
    if (worst == 0xFFFFFFFFFFFFFFFFULL) {
        worstf = __int_as_float(0x7f800000);
    } else {
        unsigned m = (unsigned)(worst >> 32);
        unsigned orig = (m & 0x80000000u) ? (m ^ 0x80000000u) : ~m;
        worstf = __uint_as_float(orig);
    }
}

// per-key accept recheck + vote + insert (called under the batched prefilter)
__device__ __forceinline__ void knn_try(unsigned skeybase,
        unsigned long long (*skey)[256], int tid, float d2, unsigned jj,
        unsigned long long* gmax, int* gslot,
        unsigned long long& worst, int& wslot, float& worstf)
{
    bool acc = d2 < worstf;      // strict: equal-d2 at larger scan idx loses anyway
    if (__any_sync(0xFFFFFFFFu, acc)) {
        unsigned ub = __float_as_uint(d2);
        ub ^= ((int)ub < 0) ? 0xFFFFFFFFu : 0x80000000u;
        unsigned long long key = ((unsigned long long)ub << 32) | jj;
        knn_insert_grp(skeybase, skey, tid, acc, key, gmax, gslot, worst, wslot, worstf);
    }
}

// ---------------- knn device fn (full scan; knn4 only) -------------------------
__device__ void knn_dev(const float* __restrict__ qb, const float* __restrict__ kb,
                        int Q, int NK, int* __restrict__ out, int qbase, char* smemraw)
{
    float4* tile = (float4*)smemraw;
    unsigned long long (*skey)[256] = (unsigned long long (*)[256])(smemraw + 16384);
    const int tid = threadIdx.x;
    const int q = qbase + tid;
    unsigned skeybase = (unsigned)__cvta_generic_to_shared(&skey[0][0]);

    float qx = qb[q], qy = qb[Q+q], qz = qb[2*Q+q];
    float q2 = __fadd_rn(__fadd_rn(__fmul_rn(qx,qx), __fmul_rn(qy,qy)), __fmul_rn(qz,qz));

    #pragma unroll
    for (int s = 0; s < 16; s++) skey[s][tid] = 0xFFFFFFFFFFFFFFFFULL;
    unsigned long long gmax[4]; int gslot[4];
    #pragma unroll
    for (int s = 0; s < 4; s++) { gmax[s] = 0xFFFFFFFFFFFFFFFFULL; gslot[s] = s<<2; }
    unsigned long long worst = 0xFFFFFFFFFFFFFFFFULL;
    float worstf = __int_as_float(0x7f800000);
    int wslot = 0;

    for (int t0 = 0; t0 < NK; t0 += 1024) {
        int tn = min(1024, NK - t0);
        __syncthreads();
        for (int i = tid; i < tn; i += 256) {
            float kx = kb[t0+i], ky = kb[NK+t0+i], kz = kb[2*NK+t0+i];
            float k2 = __fadd_rn(__fadd_rn(__fmul_rn(kx,kx), __fmul_rn(ky,ky)), __fmul_rn(kz,kz));
            tile[i] = make_float4(kx, ky, kz, k2);
        }
        __syncthreads();
        #pragma unroll 2
        for (int j = 0; j < tn; j++) {
            float d2 = knn_d2(qx, qy, qz, q2, tile[j]);
            knn_try(skeybase, skey, tid, d2, (unsigned)(t0 + j), gmax, gslot, worst, wslot, worstf);
        }
    }
    #pragma unroll
    for (int s = 0; s < 16; s++)
        out[(size_t)q*16 + s] = (int)(skey[s][tid] & 0xFFFFFFFFu);
}

// ---------------- knn split-K device fn (knn1/knn3), 4-key batched vote --------
__device__ void knn_split_dev(const float* __restrict__ qb, const float* __restrict__ kb,
                              int NK, int* __restrict__ out, int qbase, char* smemraw)
{
    float4* tile = (float4*)smemraw;
    unsigned long long (*skey)[256] = (unsigned long long (*)[256])(smemraw + 16384);
    const int tid = threadIdx.x;
    const int ql  = tid & 127;
    const int par = tid >> 7;
    const int q   = qbase + ql;
    unsigned skeybase = (unsigned)__cvta_generic_to_shared(&skey[0][0]);

    float qx = qb[q], qy = qb[NK+q], qz = qb[2*NK+q];   // self-knn: Q == NK
    float q2 = __fadd_rn(__fadd_rn(__fmul_rn(qx,qx), __fmul_rn(qy,qy)), __fmul_rn(qz,qz));

    #pragma unroll
    for (int s = 0; s < 16; s++) skey[s][tid] = 0xFFFFFFFFFFFFFFFFULL;
    unsigned long long gmax[4]; int gslot[4];
    #pragma unroll
    for (int s = 0; s < 4; s++) { gmax[s] = 0xFFFFFFFFFFFFFFFFULL; gslot[s] = s<<2; }
    unsigned long long worst = 0xFFFFFFFFFFFFFFFFULL;
    float worstf = __int_as_float(0x7f800000);
    int wslot = 0;

    for (int t0 = 0; t0 < NK; t0 += 1024) {
        int halfn = min(1024, NK - t0) >> 1;
        __syncthreads();
        for (int i = tid; i < halfn*2; i += 256) {
            float kx = kb[t0+i], ky = kb[NK+t0+i], kz = kb[2*NK+t0+i];
            float k2 = __fadd_rn(__fadd_rn(__fmul_rn(kx,kx), __fmul_rn(ky,ky)), __fmul_rn(kz,kz));
            tile[i] = make_float4(kx, ky, kz, k2);
        }
        __syncthreads();
        for (int i = 0; i < halfn; i += 4) {
            int j0 = (i << 1) | par, j1 = ((i+1) << 1) | par;
            int j2 = ((i+2) << 1) | par, j3 = ((i+3) << 1) | par;
            float4 kv0 = tile[j0], kv1 = tile[j1], kv2 = tile[j2], kv3 = tile[j3];
            float d20 = knn_d2(qx,qy,qz,q2,kv0);
            float d21 = knn_d2(qx,qy,qz,q2,kv1);
            float d22 = knn_d2(qx,qy,qz,q2,kv2);
            float d23 = knn_d2(qx,qy,qz,q2,kv3);
            // conservative prefilter vs (possibly stale) worstf; exact recheck inside
            bool pre = (d20 < worstf) | (d21 < worstf) | (d22 < worstf) | (d23 < worstf);
            if (__any_sync(0xFFFFFFFFu, pre)) {
                knn_try(skeybase, skey, tid, d20, (unsigned)(t0+j0), gmax, gslot, worst, wslot, worstf);
                knn_try(skeybase, skey, tid, d21, (unsigned)(t0+j1), gmax, gslot, worst, wslot, worstf);
                knn_try(skeybase, skey, tid, d22, (unsigned)(t0+j2), gmax, gslot, worst, wslot, worstf);
                knn_try(skeybase, skey, tid, d23, (unsigned)(t0+j3), gmax, gslot, worst, wslot, worstf);
            }
        }
    }
    __syncthreads();
    if (tid < 128) {
        for (int r = 0; r < 16; r++) {
            unsigned long long best = 0xFFFFFFFFFFFFFFFFULL; int bs = 0;
            #pragma unroll
            for (int s = 0; s < 32; s++) {
                unsigned long long vv = (s < 16) ? skey[s][tid] : skey[s-16][tid+128];
                if (vv < best) { best = vv; bs = s; }
            }
            out[(size_t)q*16 + r] = (int)(best & 0xFFFFFFFFu);
            if (bs < 16) skey[bs][tid] = 0xFFFFFFFFFFFFFFFFULL;
            else         skey[bs-16][tid+128] = 0xFFFFFFFFFFFFFFFFULL;
        }
    }
}

// ---------------- FPS (register coords; fps2 path, PPT=4) ----------------------
template<int NP, int M>
__device__ void fps_dev(const float* __restrict__ cb, int* __restrict__ outi,
                        float* __restrict__ gout, char* smemraw)
{
    constexpr int PPT = NP / 256;
    constexpr int PAIRS = PPT / 2;
    static_assert(PPT * 256 == NP && PAIRS * 2 == PPT, "layout");
    const int tid  = threadIdx.x;
    const int warp = tid >> 5;
    unsigned long long (*skeys)[8] = (unsigned long long (*)[8])smemraw;   // [2][8]

    unsigned long long xp[PAIRS], yp[PAIRS], zp[PAIRS];
    float d_[PPT];
    #pragma unroll
    for (int pr = 0; pr < PAIRS; pr++) {
        int i0 = (2*pr)*256 + tid, i1 = (2*pr+1)*256 + tid;
        xp[pr] = pk2(cb[i0],        cb[i1]);
        yp[pr] = pk2(cb[NP+i0],     cb[NP+i1]);
        zp[pr] = pk2(cb[2*NP+i0],   cb[2*NP+i1]);
        d_[2*pr] = 1e10f; d_[2*pr+1] = 1e10f;
    }
    if (tid == 0) outi[0] = 0;

    int last = 0;
    for (int t = 1; t < M; t++) {
        float px = __ldg(cb + last), py = __ldg(cb + NP + last), pz = __ldg(cb + 2*NP + last);
        unsigned long long pxn = pk2(-px, -px), pyn = pk2(-py, -py), pzn = pk2(-pz, -pz);
        float bestd = -1.0f; int besti = 0;
        #pragma unroll
        for (int pr = 0; pr < PAIRS; pr++) {
            // exact reference sequence per lane: sub, 3x mul, 2x add (NO fma)
            unsigned long long dx = addx2(xp[pr], pxn);
            unsigned long long dy = addx2(yp[pr], pyn);
            unsigned long long dz = addx2(zp[pr], pzn);
            unsigned long long s2 = addx2(addx2(mulx2(dx,dx), mulx2(dy,dy)), mulx2(dz,dz));
            float m0, m1; upk2(s2, m0, m1);
            float d0 = fminf(d_[2*pr],   m0); d_[2*pr]   = d0;
            float d1 = fminf(d_[2*pr+1], m1); d_[2*pr+1] = d1;
            if (d0 > bestd) { bestd = d0; besti = (2*pr)*256 + tid; }
            if (d1 > bestd) { bestd = d1; besti = (2*pr+1)*256 + tid; }
        }
        unsigned db     = __float_as_uint(bestd);          // d >= 0 so bits ordered
        unsigned rmax   = __reduce_max_sync(0xFFFFFFFFu, db);
        unsigned inv    = (db == rmax) ? (0xFFFFFFFFu - (unsigned)besti) : 0u;
        unsigned invmax = __reduce_max_sync(0xFFFFFFFFu, inv);
        if ((tid & 31) == 0)
            skeys[t & 1][warp] = ((unsigned long long)rmax << 32) | invmax;
        __syncthreads();
        const unsigned long long* kk = skeys[t & 1];
        unsigned long long k0 = kk[0] > kk[1] ? kk[0] : kk[1];
        unsigned long long k1 = kk[2] > kk[3] ? kk[2] : kk[3];
        unsigned long long k2 = kk[4] > kk[5] ? kk[4] : kk[5];
        unsigned long long k3 = kk[6] > kk[7] ? kk[6] : kk[7];
        k0 = k0 > k1 ? k0 : k1;
        k2 = k2 > k3 ? k2 : k3;
        k0 = k0 > k2 ? k0 : k2;
        last = (int)(0xFFFFFFFFu - (unsigned)(k0 & 0xFFFFFFFFu));
        if (tid == 0) outi[t] = last;
    }
    __syncthreads();
    for (int e = tid; e < 3*M; e += 256) {
        int c = e / M, m = e - c*M;
        gout[e] = cb[c*NP + outi[m]];
    }
}

// ---------------- FPS (shared coords; fps1 path — frees registers for 3/SM) ----
// Packed coords live in shared ([pr][xyz][tid] u64 columns; each thread reads only
// its own column -> conflict-free LDS.64, no barrier needed for coord access).
// Distance bits identical to fps_dev (same values, same rn op sequence).
template<int NP, int M>
__device__ void fps_dev_smem(const float* __restrict__ cb, int* __restrict__ outi,
                             float* __restrict__ gout, char* smemraw)
{
    constexpr int PPT = NP / 256;       // 16
    constexpr int PAIRS = PPT / 2;      // 8
    static_assert(PPT * 256 == NP && PAIRS * 2 == PPT, "layout");
    const int tid  = threadIdx.x;
    const int warp = tid >> 5;
    unsigned long long (*skeys)[8] = (unsigned long long (*)[8])smemraw;     // [2][8] @ 0
    unsigned long long* cs = (unsigned long long*)(smemraw + 128);           // [8][3][256]

    float d_[PPT];
    #pragma unroll
    for (int pr = 0; pr < PAIRS; pr++) {
        int i0 = (2*pr)*256 + tid, i1 = (2*pr+1)*256 + tid;
        cs[(pr*3+0)*256 + tid] = pk2(cb[i0],      cb[i1]);
        cs[(pr*3+1)*256 + tid] = pk2(cb[NP+i0],   cb[NP+i1]);
        cs[(pr*3+2)*256 + tid] = pk2(cb[2*NP+i0], cb[2*NP+i1]);
        d_[2*pr] = 1e10f; d_[2*pr+1] = 1e10f;
    }
    if (tid == 0) outi[0] = 0;

    int last = 0;
    for (int t = 1; t < M; t++) {
        float px = __ldg(cb + last), py = __ldg(cb + NP + last), pz = __ldg(cb + 2*NP + last);
        unsigned long long pxn = pk2(-px, -px), pyn = pk2(-py, -py), pzn = pk2(-pz, -pz);
        float bestd = -1.0f; int besti = 0;
        #pragma unroll
        for (int pr = 0; pr < PAIRS; pr++) {
            unsigned long long xv = cs[(pr*3+0)*256 + tid];
            unsigned long long yv = cs[(pr*3+1)*256 + tid];
            unsigned long long zv = cs[(pr*3+2)*256 + tid];
            unsigned long long dx = addx2(xv, pxn);
            unsigned long long dy = addx2(yv, pyn);
            unsigned long long dz = addx2(zv, pzn);
            unsigned long long s2 = addx2(addx2(mulx2(dx,dx), mulx2(dy,dy)), mulx2(dz,dz));
            float m0, m1; upk2(s2, m0, m1);
            float d0 = fminf(d_[2*pr],   m0); d_[2*pr]   = d0;
            float d1 = fminf(d_[2*pr+1], m1); d_[2*pr+1] = d1;
            if (d0 > bestd) { bestd = d0; besti = (2*pr)*256 + tid; }
            if (d1 > bestd) { bestd = d1; besti = (2*pr+1)*256 + tid; }
        }
        unsigned db     = __float_as_uint(bestd);
        unsigned rmax   = __reduce_max_sync(0xFFFFFFFFu, db);
        unsigned inv    = (db == rmax) ? (0xFFFFFFFFu - (unsigned)besti) : 0u;
        unsigned invmax = __reduce_max_sync(0xFFFFFFFFu, inv);
        if ((tid & 31) == 0)
            skeys[t & 1][warp] = ((unsigned long long)rmax << 32) | invmax;
        __syncthreads();
        const unsigned long long* kk = skeys[t & 1];
        unsigned long long k0 = kk[0] > kk[1] ? kk[0] : kk[1];
        unsigned long long k1 = kk[2] > kk[3] ? kk[2] : kk[3];
        unsigned long long k2 = kk[4] > kk[5] ? kk[4] : kk[5];
        unsigned long long k3 = kk[6] > kk[7] ? kk[6] : kk[7];
        k0 = k0 > k1 ? k0 : k1;
        k2 = k2 > k3 ? k2 : k3;
        k0 = k0 > k2 ? k0 : k2;
        last = (int)(0xFFFFFFFFu - (unsigned)(k0 & 0xFFFFFFFFu));
        if (tid == 0) outi[t] = last;
    }
    __syncthreads();
    for (int e = tid; e < 3*M; e += 256) {
        int c = e / M, m = e - c*M;
        gout[e] = cb[c*NP + outi[m]];
    }
}

// ---------------- edge conv pass 1 (generalized with query/neighbor remaps) ----
template<int C, int O>
__device__ void edge_h_dev(const float* __restrict__ kf, int nkstride,
                           const float* __restrict__ qf, int qstride,
                           const int* __restrict__ qmap, const int* __restrict__ nmap,
                           const int* __restrict__ idx, int Q,
                           const float* __restrict__ W,
                           float* __restrict__ h, float* __restrict__ stats,
                           int b, int qbase, char* smemraw)
{
    float* sW   = (float*)smemraw;      // O*2C
    float* sqf  = sW  + O*2*C;          // [c*16+ql]
    float* sqb  = sqf + C*16;           // [ql*O+o]
    float* sred = sqb + 16*O;           // 8 warps * 8

    const int tid = threadIdx.x;

    for (int i = tid; i < O*2*C; i += 256) sW[i] = W[i];
    for (int i = tid; i < C*16;  i += 256) {
        int qi = qbase + (i & 15);
        int col = qmap ? qmap[qi] : qi;
        sqf[i] = qf[((size_t)b*C + (i >> 4))*qstride + col];
    }
    __syncthreads();

    for (int e = tid; e < 16*O; e += 256) {
        int ql = e / O, o = e - ql*O;
        float acc = 0.f;
        #pragma unroll
        for (int c = 0; c < C; c++) acc = fmaf(sW[o*2*C + C + c], sqf[c*16 + ql], acc);
        sqb[e] = acc;
    }
    __syncthreads();

    const int ql = tid >> 4, k = tid & 15;
    const int q = qbase + ql;
    int j = idx[((size_t)b*Q + q)*16 + k];
    if (nmap) j = nmap[j];

    float e_[C];
    #pragma unroll
    for (int c = 0; c < C; c++)
        e_[c] = kf[((size_t)b*C + c)*nkstride + j] - sqf[c*16 + ql];

    float* hp = h + ((size_t)b*O*Q + q)*16 + k;
    const float* sqbp = sqb + ql*O;
    const int lane = tid & 31, warp = tid >> 5;

    #pragma unroll
    for (int g = 0; g < 4; g++) {
        float s = 0.f, ss = 0.f;
        for (int o = g*(O/4); o < (g+1)*(O/4); o++) {
            float acc = sqbp[o];
            const float* wr = sW + o*2*C;
            #pragma unroll
            for (int c = 0; c < C; c++) acc = fmaf(wr[c], e_[c], acc);
            hp[(size_t)o*Q*16] = acc;
            s += acc; ss = fmaf(acc, acc, ss);
        }
        #pragma unroll
        for (int off = 16; off; off >>= 1) {
            s  += __shfl_xor_sync(0xFFFFFFFFu, s,  off);
            ss += __shfl_xor_sync(0xFFFFFFFFu, ss, off);
        }
        if (lane == 0) { sred[warp*8 + g*2] = s; sred[warp*8 + g*2 + 1] = ss; }
    }
    __syncthreads();
    if (tid < 8) {
        float t = 0.f;
        #pragma unroll
        for (int w = 0; w < 8; w++) t += sred[w*8 + tid];
        atomicAdd(&stats[b*8 + tid], t);
    }
}

// ---------------- edge conv pass 2: inline GN stats + leaky + max over k -------
__device__ __forceinline__ void edge_out_dev(const float* __restrict__ h,
        const float* __restrict__ stats, float inv_cnt,
        const float* __restrict__ gamma, const float* __restrict__ beta,
        float* __restrict__ out, int O, int O4, int Q, int i)
{
    if (i >= BATCH*O*Q) return;
    int o = (i / Q) % O;
    int b = i / (Q*O);
    int g = o / O4;
    float s  = stats[b*8 + g*2];
    float ss = stats[b*8 + g*2 + 1];
    float mu  = s * inv_cnt;
    float var = ss * inv_cnt - mu*mu;
    float rstd = 1.0f / sqrtf(var + 1e-5f);
    float ga = gamma[o], be = beta[o];
    const float4* hp = (const float4*)(h + (size_t)i*16);
    float m = -INFINITY;
    #pragma unroll
    for (int r = 0; r < 4; r++) {
        float4 v = hp[r];
        float vv[4] = {v.x, v.y, v.z, v.w};
        #pragma unroll
        for (int c = 0; c < 4; c++) {
            float xn = (vv[c] - mu) * rstd;
            float y  = xn * ga + be;
            y = (y >= 0.f) ? y : 0.2f * y;
            m = fmaxf(m, y);
        }
    }
    out[i] = m;
}

__global__ void edge_out_kernel(const float* __restrict__ h, const float* __restrict__ stats,
                                float inv_cnt, const float* __restrict__ gamma,
                                const float* __restrict__ beta, float* __restrict__ out,
                                int O, int O4, int Q)
{
    edge_out_dev(h, stats, inv_cnt, gamma, beta, out, O, O4, Q, blockIdx.x*256 + threadIdx.x);
}

// ---------------- mega kernel 1: fps1-smem (0-7) || knn1 split (8-263), 3/SM ---
__global__ void __launch_bounds__(256, 3) mega1_kernel(const float* __restrict__ pc,
                                                       int* __restrict__ idx1,
                                                       int* __restrict__ fps1,
                                                       float* __restrict__ qc1)
{
    extern __shared__ char smem[];
    int blk = blockIdx.x;
    if (blk < 8) {
        fps_dev_smem<4096,1024>(pc + (size_t)blk*3*NPTS, fps1 + (size_t)blk*1024,
                                qc1 + (size_t)blk*3*1024, smem);
    } else {
        int kb = blk - 8;
        int b = kb >> 5, chunk = kb & 31;
        knn_split_dev(pc + (size_t)b*3*NPTS, pc + (size_t)b*3*NPTS, NPTS,
                      idx1 + (size_t)b*NPTS*16, chunk*128, smem);
    }
}

// ---------------- fused kernel 2: knn3 split (64) || fps2 (8) || edge1_h (2048) -
__global__ void __launch_bounds__(256) fused2_kernel(const float* __restrict__ qc1,
                                                     const float* __restrict__ feat,
                                                     const int* __restrict__ idx1,
                                                     const float* __restrict__ W1,
                                                     float* __restrict__ h,
                                                     float* __restrict__ stats0,
                                                     int* __restrict__ idx3,
                                                     int* __restrict__ fps2,
                                                     float* __restrict__ out)
{
    extern __shared__ char smem[];
    int blk = blockIdx.x;
    if (blk < 64) {
        int b = blk >> 3, chunk = blk & 7;           // 8 chunks x 128 queries
        knn_split_dev(qc1 + (size_t)b*3*1024, qc1 + (size_t)b*3*1024, 1024,
                      idx3 + (size_t)b*1024*16, chunk*128, smem);
    } else if (blk < 72) {
        int b = blk - 64;
        fps_dev<1024,256>(qc1 + (size_t)b*3*1024, fps2 + (size_t)b*256,
                          out + (size_t)b*3*256, smem);
    } else {
        int e = blk - 72;                 // 0..2047
        int b = e >> 8, qt = e & 255;
        edge_h_dev<8,32>(feat, NPTS, feat, NPTS, nullptr, nullptr, idx1, NPTS,
                         W1, h, stats0, b, qt*16, smem);
    }
}

// ---------------- combo5: edge_out1 (4096) + idx2 gather (512) -----------------
__global__ void combo5_kernel(const float* __restrict__ h, const float* __restrict__ stats0,
                              const float* __restrict__ g1, const float* __restrict__ b1,
                              float* __restrict__ kf1,
                              const int* __restrict__ idx1, const int* __restrict__ fps1,
                              int* __restrict__ idx2)
{
    int blk = blockIdx.x;
    if (blk < 4096) {
        edge_out_dev(h, stats0, 1.0f/524288.0f, g1, b1, kf1, 32, 8, NPTS,
                     blk*256 + threadIdx.x);
    } else {
        int i = (blk - 4096)*256 + threadIdx.x;      // over B*1024*16
        if (i < BATCH*1024*16) {
            int s = i & 15; int m = (i >> 4) & 1023; int b = i >> 14;
            idx2[i] = idx1[((size_t)b*NPTS + fps1[b*1024 + m])*16 + s];
        }
    }
}

// ---------------- kernel6: knn4 (0-7, on out coords) || edge_h2 (8-519) --------
__global__ void __launch_bounds__(256) kernel6(const float* __restrict__ out,
                                               int* __restrict__ idx4,
                                               const float* __restrict__ kf1,
                                               const int* __restrict__ fps1,
                                               const int* __restrict__ idx2,
                                               const float* __restrict__ W2,
                                               float* __restrict__ h,
                                               float* __restrict__ stats1)
{
    extern __shared__ char smem[];
    int blk = blockIdx.x;
    if (blk < 8) {
        knn_dev(out + (size_t)blk*3*256, out + (size_t)blk*3*256, 256, 256,
                idx4 + (size_t)blk*256*16, 0, smem);
    } else {
        int e = blk - 8;                  // 0..511
        int b = e >> 6, qt = e & 63;
        edge_h_dev<32,64>(kf1, NPTS, kf1, NPTS, fps1 + b*1024, nullptr, idx2, 1024,
                          W2, h, stats1, b, qt*16, smem);
    }
}

// ---------------- edge_h wrappers (stages 3,4) ---------------------------------
__global__ void edge_h3_kernel(const float* __restrict__ qf2, const int* __restrict__ idx3,
                               const float* __restrict__ W3, float* __restrict__ h,
                               float* __restrict__ stats2)
{
    extern __shared__ char smemc[];
    edge_h_dev<64,64>(qf2, 1024, qf2, 1024, nullptr, nullptr, idx3, 1024,
                      W3, h, stats2, blockIdx.y, blockIdx.x*16, smemc);
}

__global__ void edge_h4_kernel(const float* __restrict__ kf3, const int* __restrict__ fps2,
                               const int* __restrict__ idx4, const float* __restrict__ W4,
                               float* __restrict__ h, float* __restrict__ stats3)
{
    extern __shared__ char smemc[];
    int b = blockIdx.y;
    edge_h_dev<64,128>(kf3, 1024, kf3, 1024, fps2 + b*256, fps2 + b*256, idx4, 256,
                       W4, h, stats3, b, blockIdx.x*16, smemc);
}

// ---------------- host orchestration ----------------
static inline int eh_smem(int C, int O) { return (O*2*C + 16*C + 16*O + 64) * 4; }
#define KNN_SMEM  49152
#define MEGA_SMEM 49280   // 128B skeys + 48KB fps coords (knn uses first 48KB only)

extern "C" void kernel_launch(void* const* d_in, const int* in_sizes, int n_in,
                              void* d_out, int out_size)
{
    const float* pc = (const float*)d_in[0];
    const float* Wt = (const float*)d_in[1];
    const float* bt = (const float*)d_in[2];
    const float* W1 = (const float*)d_in[3];
    const float* g1 = (const float*)d_in[4];
    const float* b1 = (const float*)d_in[5];
    const float* W2 = (const float*)d_in[6];
    const float* g2 = (const float*)d_in[7];
    const float* b2 = (const float*)d_in[8];
    const float* W3 = (const float*)d_in[9];
    const float* g3 = (const float*)d_in[10];
    const float* b3 = (const float*)d_in[11];
    const float* W4 = (const float*)d_in[12];
    const float* g4 = (const float*)d_in[13];
    const float* b4 = (const float*)d_in[14];
    float* out = (float*)d_out;

    float *feat, *h, *kf1, *qc1, *qf2, *kf3, *stats, *musig;
    int *idx1, *idx2, *idx3, *idx4, *fps1, *fps2;
    cudaGetSymbolAddress((void**)&feat,  g_feat);
    cudaGetSymbolAddress((void**)&h,     g_h);
    cudaGetSymbolAddress((void**)&kf1,   g_kf1);
    cudaGetSymbolAddress((void**)&qc1,   g_qc1);
    cudaGetSymbolAddress((void**)&qf2,   g_qf2);
    cudaGetSymbolAddress((void**)&kf3,   g_kf3);
    cudaGetSymbolAddress((void**)&stats, g_stats);
    cudaGetSymbolAddress((void**)&musig, g_musig);
    cudaGetSymbolAddress((void**)&idx1,  g_idx1);
    cudaGetSymbolAddress((void**)&idx2,  g_idx2);
    cudaGetSymbolAddress((void**)&idx3,  g_idx3);
    cudaGetSymbolAddress((void**)&idx4,  g_idx4);
    cudaGetSymbolAddress((void**)&fps1,  g_fps1);
    cudaGetSymbolAddress((void**)&fps2,  g_fps2);

    float* st0 = stats;          // stage 1
    float* st1 = stats + 64;     // stage 2
    float* st2 = stats + 128;    // stage 3
    float* st3 = stats + 192;    // stage 4

    cudaFuncSetAttribute(mega1_kernel,
                         cudaFuncAttributeMaxDynamicSharedMemorySize, MEGA_SMEM);
    cudaFuncSetAttribute(edge_h4_kernel,
                         cudaFuncAttributeMaxDynamicSharedMemorySize, eh_smem(64,128));

    // 1: transform + stats zero
    transform_kernel<<<(BATCH*8*NPTS+255)/256, 256>>>(pc, Wt, bt, feat, stats);
    // 2-3: pads (keep mega1 in the ncu capture slot)
    pad_kernel<<<1,64>>>(musig);
    pad_kernel<<<1,64>>>(musig);

    // 4: mega1 = fps1 (smem coords, writes qc1) || knn1 split-K, 3 blocks/SM
    mega1_kernel<<<264, 256, MEGA_SMEM>>>(pc, idx1, fps1, qc1);

    // 5: fused2 = knn3 split || fps2 (writes out coords) || edge1_h
    fused2_kernel<<<2120, 256, KNN_SMEM>>>(qc1, feat, idx1, W1, h, st0, idx3, fps2, out);

    // 6: edge_out1 (-> kf1) + idx2 = idx1[fps1]
    combo5_kernel<<<4608, 256>>>(h, st0, g1, b1, kf1, idx1, fps1, idx2);

    // 7: knn4 (on out coords) + edge_h2 (queries remapped via fps1)
    kernel6<<<520, 256, KNN_SMEM>>>(out, idx4, kf1, fps1, idx2, W2, h, st1);

    // 8: edge_out2 -> qf2
    edge_out_kernel<<<(BATCH*64*1024+255)/256, 256>>>(h, st1, 1.0f/262144.0f, g2, b2, qf2, 64, 16, 1024);

    // 9: edge_h3
    edge_h3_kernel<<<dim3(64, BATCH), 256, eh_smem(64,64)>>>(qf2, idx3, W3, h, st2);

    // 10: edge_out3 -> kf3
    edge_out_kernel<<<(BATCH*64*1024+255)/256, 256>>>(h, st2, 1.0f/262144.0f, g3, b3, kf3, 64, 16, 1024);

    // 11: edge_h4 (queries+neighbors remapped via fps2)
    edge_h4_kernel<<<dim3(16, BATCH), 256, eh_smem(64,128)>>>(kf3, fps2, idx4, W4, h, st3);

    // 12: edge_out4 -> out features
    edge_out_kernel<<<(BATCH*128*256+255)/256, 256>>>(h, st3, 1.0f/131072.0f, g4, b4,
                                                      out + BATCH*3*256, 128, 32, 256);
}